// round 6
// baseline (speedup 1.0000x reference)
#include <cuda_runtime.h>
#include <cuda_bf16.h>
#include <math.h>
#include <stdint.h>

#define Bq   8
#define Nn   1024
#define Dm   896
#define Hh   14
#define Dh   64
#define BN   (Bq*Nn)          // 8192
#define KCAT 2688             // 3*896 split-bf16 concat
#define QT   16
#define EPITCH 132            // epilogue f32 smem pitch
#define STG  20480            // bytes per pipeline stage (A 10240 + B 10240)

// -------------------- device scratch --------------------
__device__ __align__(128) __nv_bfloat16 g_xcat[(size_t)BN*KCAT];   // [hi|hi|lo] of LN(x)
__device__ __align__(128) __nv_bfloat16 g_wqkv[(size_t)KCAT*KCAT]; // [n][k] packed [Whi|Wlo|Whi]
__device__ __align__(128) __nv_bfloat16 g_wocat[(size_t)Dm*KCAT];
__device__ __align__(128) __nv_bfloat16 g_aocat[(size_t)BN*KCAT];  // attention out, packed split
__device__ float g_Q[(size_t)Bq*Hh*Nn*Dh];
__device__ float g_K[(size_t)Bq*Hh*Nn*Dh];
__device__ float g_V[(size_t)Bq*Hh*Nn*Dh];
__device__ float g_align[(size_t)Bq*Nn*Nn];
__device__ float g_revb[Nn*Nn];
__device__ float g_cos[Nn*32];
__device__ float g_sin[Nn*32];

// -------------------- PTX helpers (base ISA only) --------------------
__device__ __forceinline__ uint32_t smem_u32(const void* p) {
    uint32_t a;
    asm("{ .reg .u64 t; cvta.to.shared.u64 t, %1; cvt.u32.u64 %0, t; }" : "=r"(a) : "l"(p));
    return a;
}
__device__ __forceinline__ void cp_async16(uint32_t dst, const void* src) {
    asm volatile("cp.async.cg.shared.global [%0], [%1], 16;" :: "r"(dst), "l"(src));
}
#define CP_COMMIT() asm volatile("cp.async.commit_group;" ::: "memory")
#define CP_WAIT0()  asm volatile("cp.async.wait_group 0;" ::: "memory")
#define CP_WAIT1()  asm volatile("cp.async.wait_group 1;" ::: "memory")

__device__ __forceinline__ void ldsm_x4(uint32_t a, uint32_t* r) {
    asm volatile("ldmatrix.sync.aligned.m8n8.x4.shared.b16 {%0,%1,%2,%3}, [%4];"
                 : "=r"(r[0]), "=r"(r[1]), "=r"(r[2]), "=r"(r[3]) : "r"(a));
}
__device__ __forceinline__ void ldsm_x2(uint32_t a, uint32_t* r) {
    asm volatile("ldmatrix.sync.aligned.m8n8.x2.shared.b16 {%0,%1}, [%2];"
                 : "=r"(r[0]), "=r"(r[1]) : "r"(a));
}
__device__ __forceinline__ void mma16816(float* c, const uint32_t* a, const uint32_t* b) {
    asm volatile("mma.sync.aligned.m16n8k16.row.col.f32.bf16.bf16.f32 "
                 "{%0,%1,%2,%3},{%4,%5,%6,%7},{%8,%9},{%0,%1,%2,%3};"
                 : "+f"(c[0]), "+f"(c[1]), "+f"(c[2]), "+f"(c[3])
                 : "r"(a[0]), "r"(a[1]), "r"(a[2]), "r"(a[3]), "r"(b[0]), "r"(b[1]));
}

// -------------------- MUFU-free math --------------------
// exp(x) via 2^n * poly(f): ~9 FMA/ALU ops, no MUFU. rel err ~1e-7.
__device__ __forceinline__ float fexp(float x) {
    x = fmaxf(x, -80.f);
    float y = x * 1.442695041f;
    float n = rintf(y);
    float f = y - n;
    float p =            1.8775767e-3f;
    p = fmaf(p, f, 8.9893397e-3f);
    p = fmaf(p, f, 5.5826318e-2f);
    p = fmaf(p, f, 2.4015361e-1f);
    p = fmaf(p, f, 6.9315308e-1f);
    p = fmaf(p, f, 9.9999994e-1f);
    return __int_as_float(__float_as_int(p) + ((int)n << 23));
}
// tanh(x) = sign(x) * (1-e)/(1+e), e = exp(-2|x|); reciprocal of d in [1,2]
// via linear seed + 3 Newton steps. No MUFU. abs err ~1e-7.
__device__ __forceinline__ float ftanh(float x) {
    float ax = fabsf(x);
    float e = fexp(-2.f * ax);
    float d = 1.f + e;
    float r = fmaf(-0.5f, d, 1.4571f);
    r = r * fmaf(-d, r, 2.f);
    r = r * fmaf(-d, r, 2.f);
    r = r * fmaf(-d, r, 2.f);
    float t = (1.f - e) * r;
    return (x >= 0.f) ? t : -t;
}

// -------------------- split helper --------------------
__device__ __forceinline__ void split3(__nv_bfloat16* p, float v) {
    __nv_bfloat16 hi = __float2bfloat16(v);
    __nv_bfloat16 lo = __float2bfloat16(v - __bfloat162float(hi));
    p[0] = hi; p[Dm] = hi; p[2*Dm] = lo;
}

// -------------------- LayerNorm + split-pack --------------------
__global__ void ln_split_kernel(const float* __restrict__ x, const float* __restrict__ g,
                                const float* __restrict__ bb, __nv_bfloat16* __restrict__ y)
{
    int row = blockIdx.x;
    const float* xr = x + (size_t)row * Dm;
    float s = 0.f, s2 = 0.f;
    for (int i = threadIdx.x; i < Dm; i += 256) { float v = xr[i]; s += v; s2 += v*v; }
    #pragma unroll
    for (int o = 16; o; o >>= 1) { s += __shfl_xor_sync(~0u, s, o); s2 += __shfl_xor_sync(~0u, s2, o); }
    __shared__ float ws[8], ws2[8];
    int w = threadIdx.x >> 5;
    if ((threadIdx.x & 31) == 0) { ws[w] = s; ws2[w] = s2; }
    __syncthreads();
    if (threadIdx.x < 32) {
        s  = (threadIdx.x < 8) ? ws[threadIdx.x]  : 0.f;
        s2 = (threadIdx.x < 8) ? ws2[threadIdx.x] : 0.f;
        #pragma unroll
        for (int o = 4; o; o >>= 1) { s += __shfl_xor_sync(~0u, s, o); s2 += __shfl_xor_sync(~0u, s2, o); }
        if (threadIdx.x == 0) { ws[0] = s; ws2[0] = s2; }
    }
    __syncthreads();
    float mu  = ws[0] * (1.f/Dm);
    float var = ws2[0] * (1.f/Dm) - mu*mu;
    float inv = rsqrtf(var + 1e-5f);
    __nv_bfloat16* yr = y + (size_t)row * KCAT;
    for (int i = threadIdx.x; i < Dm; i += 256) {
        float v = (xr[i] - mu) * inv * g[i] + bb[i];
        split3(yr + i, v);
    }
}

// -------------------- weight transforms --------------------
__global__ void wcat_qkv_kernel(const float* __restrict__ Wq, const float* __restrict__ Wk,
                                const float* __restrict__ Wv, __nv_bfloat16* __restrict__ out)
{
    size_t idx = (size_t)blockIdx.x * 256 + threadIdx.x;
    if (idx >= (size_t)KCAT * KCAT) return;
    int k = (int)(idx % KCAT);
    int n = (int)(idx / KCAT);
    const float* W = (n < Dm) ? Wq : ((n < 2*Dm) ? Wk : Wv);
    int c = n % Dm;
    int kr = k % Dm;
    int blk = k / Dm;
    float w = W[(size_t)kr * Dm + c];
    __nv_bfloat16 hi = __float2bfloat16(w);
    out[idx] = (blk == 1) ? __float2bfloat16(w - __bfloat162float(hi)) : hi;
}
__global__ void wcat_o_kernel(const float* __restrict__ Wo, __nv_bfloat16* __restrict__ out)
{
    size_t idx = (size_t)blockIdx.x * 256 + threadIdx.x;
    if (idx >= (size_t)Dm * KCAT) return;
    int k = (int)(idx % KCAT);
    int n = (int)(idx / KCAT);
    int kr = k % Dm;
    int blk = k / Dm;
    float w = Wo[(size_t)kr * Dm + n];
    __nv_bfloat16 hi = __float2bfloat16(w);
    out[idx] = (blk == 1) ? __float2bfloat16(w - __bfloat162float(hi)) : hi;
}

// -------------------- RoPE / bearings / alignment prep --------------------
__global__ void rope_tab_kernel(float* __restrict__ cc, float* __restrict__ ss)
{
    int i = blockIdx.x * 256 + threadIdx.x;
    if (i >= Nn * 32) return;
    int n = i >> 5, d = i & 31;
    float freq = (float)n * powf(10000.f, -(float)(2*d) / 64.f);
    cc[i] = cosf(freq);
    ss[i] = sinf(freq);
}
__global__ void revb_kernel(const float* __restrict__ bearings, float* __restrict__ revb)
{
    __shared__ float t[32][33];
    int bx = blockIdx.x * 32, by = blockIdx.y * 32;
    int x = bx + threadIdx.x, y = by + threadIdx.y;
    t[threadIdx.y][threadIdx.x] = bearings[(size_t)y * Nn + x];
    __syncthreads();
    int oq = bx + threadIdx.y, ok = by + threadIdx.x;
    revb[(size_t)oq * Nn + ok] = fmodf(t[threadIdx.x][threadIdx.y] + 180.f, 360.f);
}
__global__ void align_kernel(const float* __restrict__ wd, const float* __restrict__ revb,
                             float* __restrict__ al)
{
    size_t i = (size_t)blockIdx.x * 256 + threadIdx.x;
    int b = blockIdx.y;
    int q = (int)(i >> 10);
    float a = (wd[b*Nn + q] - revb[i]) * 0.017453292519943295f;
    al[((size_t)b << 20) + i] = cosf(a);
}

// -------------------- stage loader: A 128x32, B 128x32 (pitch 80B) --------------------
__device__ __forceinline__ void load_stage(uint32_t abase, uint32_t bbase,
                                           const __nv_bfloat16* __restrict__ A,
                                           const __nv_bfloat16* __restrict__ Bw,
                                           int m0, int n0, int k0)
{
    int tid = threadIdx.x;
    #pragma unroll
    for (int p = 0; p < 2; p++) {
        int e = p * 256 + tid;
        int r = e >> 2, seg = e & 3;
        cp_async16(abase + r * 80 + seg * 16,
                   A + (size_t)(m0 + r) * KCAT + k0 + seg * 8);
    }
    #pragma unroll
    for (int p = 0; p < 2; p++) {
        int e = p * 256 + tid;
        int r = e >> 2, seg = e & 3;
        cp_async16(bbase + r * 80 + seg * 16,
                   Bw + (size_t)(n0 + r) * KCAT + k0 + seg * 8);
    }
}

// -------------------- mma.sync GEMM, 128x128 tile, 3-stage, occ 2 --------------------
template<int MODE>
__global__ void __launch_bounds__(256, 2)
gemm_mma(const __nv_bfloat16* __restrict__ A, const __nv_bfloat16* __restrict__ Bw,
         const float* __restrict__ cosp, const float* __restrict__ sinp,
         const float* __restrict__ res,
         float* __restrict__ outQ, float* __restrict__ outK, float* __restrict__ outV)
{
    extern __shared__ char dsm[];
    uint32_t sb = smem_u32(dsm);
    float* sep = (float*)dsm;

    int tid = threadIdx.x, wid = tid >> 5, lane = tid & 31;
    int wm = wid >> 2, wn = wid & 3;            // warp: 64-row half, 32-col quarter
    int m0 = blockIdx.y * 128, n0 = blockIdx.x * 128;

    float acc[4][4][4];
    #pragma unroll
    for (int i = 0; i < 4; i++)
        #pragma unroll
        for (int j = 0; j < 4; j++)
            #pragma unroll
            for (int r = 0; r < 4; r++) acc[i][j][r] = 0.f;

    // lane-fixed ldmatrix offsets (bytes) within a stage
    int gq = lane >> 3, lr = lane & 7;
    uint32_t a_off = (uint32_t)((wm*64 + lr + (gq & 1)*8) * 80 + (gq >> 1)*16);
    uint32_t b_off = (uint32_t)((wn*32 + lr) * 80 + ((lane & 8) ? 16 : 0));

    load_stage(sb + 0*STG, sb + 0*STG + 10240, A, Bw, m0, n0, 0);
    CP_COMMIT();
    load_stage(sb + 1*STG, sb + 1*STG + 10240, A, Bw, m0, n0, 32);
    CP_COMMIT();

    const int NT = KCAT / 32;   // 84
    int slot = 0;
    for (int i = 0; i < NT; i++) {
        if (i + 1 < NT) CP_WAIT1(); else CP_WAIT0();
        __syncthreads();

        uint32_t ab = sb + slot * STG, bb = ab + 10240;
        #pragma unroll
        for (int ks = 0; ks < 2; ks++) {
            uint32_t afr[4][4], bfr[4][2];
            #pragma unroll
            for (int mt = 0; mt < 4; mt++)
                ldsm_x4(ab + a_off + mt*(16*80) + ks*32, afr[mt]);
            #pragma unroll
            for (int nt = 0; nt < 4; nt++)
                ldsm_x2(bb + b_off + nt*(8*80) + ks*32, bfr[nt]);
            #pragma unroll
            for (int mt = 0; mt < 4; mt++)
                #pragma unroll
                for (int nt = 0; nt < 4; nt++)
                    mma16816(acc[mt][nt], afr[mt], bfr[nt]);
        }

        if (i + 2 < NT) {
            int ns = slot + 2; if (ns >= 3) ns -= 3;
            uint32_t nb = sb + ns * STG;
            load_stage(nb, nb + 10240, A, Bw, m0, n0, (i + 2) * 32);
            CP_COMMIT();
        }
        slot++; if (slot == 3) slot = 0;
    }
    __syncthreads();

    // epilogue in two 64-row passes (staging fits inside pipeline smem)
    #pragma unroll
    for (int half = 0; half < 2; half++) {
        if (wm == half) {
            #pragma unroll
            for (int mt = 0; mt < 4; mt++)
                #pragma unroll
                for (int nt = 0; nt < 4; nt++)
                    #pragma unroll
                    for (int ri = 0; ri < 4; ri++) {
                        int r = mt*16 + (lane >> 2) + ((ri >> 1) * 8);
                        int n = wn*32 + nt*8 + ((lane & 3) * 2) + (ri & 1);
                        sep[r * EPITCH + n] = acc[mt][nt][ri];
                    }
        }
        __syncthreads();

        if (MODE == 0) {
            int tile = blockIdx.x;          // 0..20
            int region = tile / 7;          // 0=Q 1=K 2=V
            int cbase = (tile % 7) * 128;
            float* base = (region == 0) ? outQ : ((region == 1) ? outK : outV);
            for (int idx = tid; idx < 64*128; idx += 256) {
                int r = idx >> 7, c = idx & 127;
                int m = m0 + half*64 + r;
                int b = m >> 10, n = m & 1023;
                int cc = cbase + c;
                int head = cc >> 6, d = cc & 63;
                float val;
                if (region < 2) {
                    if (d < 32) {
                        float x1 = sep[r*EPITCH + c], x2 = sep[r*EPITCH + c + 32];
                        val = x1 * cosp[n*32 + d] - x2 * sinp[n*32 + d];
                    } else {
                        float x2 = sep[r*EPITCH + c], x1 = sep[r*EPITCH + c - 32];
                        int dd = d - 32;
                        val = x2 * cosp[n*32 + dd] + x1 * sinp[n*32 + dd];
                    }
                } else {
                    val = sep[r*EPITCH + c];
                }
                base[(((size_t)b * Hh + head) * Nn + n) * Dh + d] = val;
            }
        } else {
            for (int idx = tid; idx < 64*128; idx += 256) {
                int r = idx >> 7, c = idx & 127;
                int m = m0 + half*64 + r;
                size_t o = (size_t)m * Dm + n0 + c;
                outQ[o] = sep[r*EPITCH + c] + res[o];
            }
        }
        __syncthreads();
    }
}

// -------------------- fused attention: QT=16, 512 threads, MUFU-free --------------------
__global__ void __launch_bounds__(512, 2)
attn_kernel(const float* __restrict__ Q, const float* __restrict__ K,
            const float* __restrict__ V, const float* __restrict__ adj,
            const float* __restrict__ al, const float* __restrict__ wind_w,
            const float* __restrict__ wind_b, __nv_bfloat16* __restrict__ out)
{
    int h = blockIdx.y, b = blockIdx.z;
    int q0 = blockIdx.x * QT;
    int tid = threadIdx.x;
    const float w0 = wind_w[h], w1 = wind_w[Hh + h], wb = wind_b[h];
    const size_t bh = ((size_t)b * Hh + h) * Nn;
    const float* Kb = K + bh * Dh;
    const float* Vb = V + bh * Dh;

    extern __shared__ float smf[];
    float* sc = smf;                    // [QT][Nn]
    float* qsm = smf + QT * Nn;         // [QT][Dh]
    float* rowsum = qsm + QT * Dh;      // [QT]

    for (int i = tid; i < QT * Dh; i += 512)
        qsm[i] = Q[(bh + q0 + (i >> 6)) * Dh + (i & 63)];
    __syncthreads();

    // ---- scores + bias (poly tanh, no MUFU) ----
    for (int k = tid; k < Nn; k += 512) {
        const float4* kr4 = (const float4*)(Kb + (size_t)k * Dh);
        float acc[QT];
        #pragma unroll
        for (int qi = 0; qi < QT; qi++) acc[qi] = 0.f;
        #pragma unroll
        for (int d4 = 0; d4 < 16; d4++) {
            float4 kv = kr4[d4];
            #pragma unroll
            for (int qi = 0; qi < QT; qi++) {
                float4 qv = ((const float4*)(qsm + qi * Dh))[d4];
                acc[qi] += qv.x*kv.x + qv.y*kv.y + qv.z*kv.z + qv.w*kv.w;
            }
        }
        #pragma unroll
        for (int qi = 0; qi < QT; qi++) {
            int q = q0 + qi;
            float a  = adj[(size_t)q * Nn + k];
            float av = al[((size_t)b << 20) + (size_t)q * Nn + k];
            float bias = ftanh(av * w0 + a * w1 + wb);
            float s = (a > 0.f) ? acc[qi] * 0.125f : -1e30f;
            sc[qi * Nn + k] = s + bias;
        }
    }
    __syncthreads();

    // ---- softmax: one warp per query row (16 warps), poly exp ----
    int wid = tid >> 5, lane = tid & 31;
    {
        float* row = sc + wid * Nn;
        float mx = -1e30f;
        for (int k = lane; k < Nn; k += 32) mx = fmaxf(mx, row[k]);
        #pragma unroll
        for (int o = 16; o; o >>= 1) mx = fmaxf(mx, __shfl_xor_sync(~0u, mx, o));
        float sm = 0.f;
        for (int k = lane; k < Nn; k += 32) {
            float e = fexp(row[k] - mx);
            row[k] = e;
            sm += e;
        }
        #pragma unroll
        for (int o = 16; o; o >>= 1) sm += __shfl_xor_sync(~0u, sm, o);
        if (lane == 0) rowsum[wid] = sm;
    }
    __syncthreads();

    // ---- PV: warp per query, lane = (d4, khalf), float4 V ----
    {
        int q = wid;
        int d4 = lane & 15, kh = lane >> 4;
        const float4* v4 = (const float4*)Vb;
        const float* row = sc + q * Nn;
        float4 a4 = make_float4(0.f, 0.f, 0.f, 0.f);
        int k0 = kh * 512;
        #pragma unroll 4
        for (int k = k0; k < k0 + 512; k++) {
            float4 vv = v4[(size_t)k * 16 + d4];
            float s = row[k];
            a4.x += s * vv.x; a4.y += s * vv.y; a4.z += s * vv.z; a4.w += s * vv.w;
        }
        a4.x += __shfl_xor_sync(~0u, a4.x, 16);
        a4.y += __shfl_xor_sync(~0u, a4.y, 16);
        a4.z += __shfl_xor_sync(~0u, a4.z, 16);
        a4.w += __shfl_xor_sync(~0u, a4.w, 16);
        if (kh == 0) {
            float inv = 1.f / rowsum[q];
            float o0 = a4.x * inv, o1 = a4.y * inv, o2 = a4.z * inv, o3 = a4.w * inv;
            int col = h * 64 + d4 * 4;
            __nv_bfloat16* p = out + (size_t)(b * Nn + q0 + q) * KCAT + col;
            __nv_bfloat16 h0 = __float2bfloat16(o0), h1 = __float2bfloat16(o1);
            __nv_bfloat16 h2 = __float2bfloat16(o2), h3 = __float2bfloat16(o3);
            __nv_bfloat162 hi01 = __nv_bfloat162(h0, h1), hi23 = __nv_bfloat162(h2, h3);
            __nv_bfloat162 lo01 = __nv_bfloat162(
                __float2bfloat16(o0 - __bfloat162float(h0)),
                __float2bfloat16(o1 - __bfloat162float(h1)));
            __nv_bfloat162 lo23 = __nv_bfloat162(
                __float2bfloat16(o2 - __bfloat162float(h2)),
                __float2bfloat16(o3 - __bfloat162float(h3)));
            ((__nv_bfloat162*)(p))[0] = hi01;       ((__nv_bfloat162*)(p))[1] = hi23;
            ((__nv_bfloat162*)(p + Dm))[0] = hi01;  ((__nv_bfloat162*)(p + Dm))[1] = hi23;
            ((__nv_bfloat162*)(p + 2*Dm))[0] = lo01;((__nv_bfloat162*)(p + 2*Dm))[1] = lo23;
        }
    }
}

// -------------------- launch --------------------
extern "C" void kernel_launch(void* const* d_in, const int* in_sizes, int n_in,
                              void* d_out, int out_size)
{
    const float* node = (const float*)d_in[0];
    const float* adj  = (const float*)d_in[1];
    const float* wd   = (const float*)d_in[2];
    const float* bear = (const float*)d_in[3];
    const float* Wq   = (const float*)d_in[4];
    const float* Wk   = (const float*)d_in[5];
    const float* Wv   = (const float*)d_in[6];
    const float* Wo   = (const float*)d_in[7];
    const float* lng  = (const float*)d_in[8];
    const float* lnb  = (const float*)d_in[9];
    const float* ww   = (const float*)d_in[10];
    const float* wbv  = (const float*)d_in[11];
    float* out = (float*)d_out;

    __nv_bfloat16 *xcat, *wqkv, *wocat, *aocat;
    float *Qp, *Kp, *Vp, *alp, *revb, *cosp, *sinp;
    cudaGetSymbolAddress((void**)&xcat,  g_xcat);
    cudaGetSymbolAddress((void**)&wqkv,  g_wqkv);
    cudaGetSymbolAddress((void**)&wocat, g_wocat);
    cudaGetSymbolAddress((void**)&aocat, g_aocat);
    cudaGetSymbolAddress((void**)&Qp,    g_Q);
    cudaGetSymbolAddress((void**)&Kp,    g_K);
    cudaGetSymbolAddress((void**)&Vp,    g_V);
    cudaGetSymbolAddress((void**)&alp,   g_align);
    cudaGetSymbolAddress((void**)&revb,  g_revb);
    cudaGetSymbolAddress((void**)&cosp,  g_cos);
    cudaGetSymbolAddress((void**)&sinp,  g_sin);

    const int SMEM_GEMM = 3 * STG;                       // 61440
    const int SMEM_ATTN = (QT*Nn + QT*Dh + 16) * 4;      // ~69.7 KB
    cudaFuncSetAttribute(gemm_mma<0>, cudaFuncAttributeMaxDynamicSharedMemorySize, SMEM_GEMM);
    cudaFuncSetAttribute(gemm_mma<1>, cudaFuncAttributeMaxDynamicSharedMemorySize, SMEM_GEMM);
    cudaFuncSetAttribute(attn_kernel, cudaFuncAttributeMaxDynamicSharedMemorySize, SMEM_ATTN);

    // Launch order arranged so gemm_mma<0> is the 4th launch (profiler captures #4).
    // 1: rope tables (needed by gemm0 epilogue)
    rope_tab_kernel<<<(Nn*32 + 255)/256, 256>>>(cosp, sinp);
    // 2: QKV weight split-pack
    wcat_qkv_kernel<<<(int)(((size_t)KCAT*KCAT + 255)/256), 256>>>(Wq, Wk, Wv, wqkv);
    // 3: LN + split
    ln_split_kernel<<<BN, 256>>>(node, lng, lnb, xcat);
    // 4: fused QKV tensor GEMM (PROFILED)
    gemm_mma<0><<<dim3(KCAT/128, BN/128), 256, SMEM_GEMM>>>(xcat, wqkv, cosp, sinp,
                                                            nullptr, Qp, Kp, Vp);
    // 5,6: bearing transpose + alignment (needed by attn only)
    revb_kernel<<<dim3(32, 32), dim3(32, 32)>>>(bear, revb);
    align_kernel<<<dim3(4096, Bq), 256>>>(wd, revb, alp);
    // 7: O-proj weight split-pack (needed by gemm1 only)
    wcat_o_kernel<<<(int)(((size_t)Dm*KCAT + 255)/256), 256>>>(Wo, wocat);
    // 8: fused attention (writes split-packed ao)
    attn_kernel<<<dim3(Nn/QT, Hh, Bq), 512, SMEM_ATTN>>>(Qp, Kp, Vp, adj, alp, ww, wbv, aocat);
    // 9: output projection + residual (tensor)
    gemm_mma<1><<<dim3(Dm/128, BN/128), 256, SMEM_GEMM>>>(aocat, wocat, cosp, sinp,
                                                          node, out, nullptr, nullptr);
}

// round 7
// speedup vs baseline: 1.1914x; 1.1914x over previous
#include <cuda_runtime.h>
#include <cuda_bf16.h>
#include <math.h>
#include <stdint.h>

#define Bq   8
#define Nn   1024
#define Dm   896
#define Hh   14
#define Dh   64
#define BN   (Bq*Nn)
#define KCAT 2688
#define EPITCH 132
#define STG  20480
#define SCP  1032

__device__ __align__(128) __nv_bfloat16 g_xcat[(size_t)BN*KCAT];
__device__ __align__(128) __nv_bfloat16 g_wqkv[(size_t)KCAT*KCAT];
__device__ __align__(128) __nv_bfloat16 g_wocat[(size_t)Dm*KCAT];
__device__ __align__(128) __nv_bfloat16 g_aocat[(size_t)BN*KCAT];
__device__ __align__(128) __nv_bfloat16 g_Qc[(size_t)Bq*Hh*Nn*128];
__device__ __align__(128) __nv_bfloat16 g_Kc[(size_t)Bq*Hh*Nn*128];
__device__ __align__(128) __nv_bfloat16 g_Vc[(size_t)Bq*Hh*Nn*128];
__device__ float g_align[(size_t)Bq*Nn*Nn];
__device__ float g_cos[Nn*32];
__device__ float g_sin[Nn*32];

__device__ __forceinline__ uint32_t smem_u32(const void* p) {
    uint32_t a;
    asm("{ .reg .u64 t; cvta.to.shared.u64 t, %1; cvt.u32.u64 %0, t; }" : "=r"(a) : "l"(p));
    return a;
}
__device__ __forceinline__ void cp_async16(uint32_t dst, const void* src) {
    asm volatile("cp.async.cg.shared.global [%0], [%1], 16;" :: "r"(dst), "l"(src));
}
#define CP_COMMIT() asm volatile("cp.async.commit_group;" ::: "memory")
#define CP_WAIT0()  asm volatile("cp.async.wait_group 0;" ::: "memory")
#define CP_WAIT1()  asm volatile("cp.async.wait_group 1;" ::: "memory")

__device__ __forceinline__ void ldsm_x4(uint32_t a, uint32_t* r) {
    asm volatile("ldmatrix.sync.aligned.m8n8.x4.shared.b16 {%0,%1,%2,%3}, [%4];"
                 : "=r"(r[0]), "=r"(r[1]), "=r"(r[2]), "=r"(r[3]) : "r"(a));
}
__device__ __forceinline__ void ldsm_x2(uint32_t a, uint32_t* r) {
    asm volatile("ldmatrix.sync.aligned.m8n8.x2.shared.b16 {%0,%1}, [%2];"
                 : "=r"(r[0]), "=r"(r[1]) : "r"(a));
}
__device__ __forceinline__ void ldsm_x4t(uint32_t a, uint32_t* r) {
    asm volatile("ldmatrix.sync.aligned.m8n8.x4.trans.shared.b16 {%0,%1,%2,%3}, [%4];"
                 : "=r"(r[0]), "=r"(r[1]), "=r"(r[2]), "=r"(r[3]) : "r"(a));
}
__device__ __forceinline__ void mma16816(float* c, const uint32_t* a, const uint32_t* b) {
    asm volatile("mma.sync.aligned.m16n8k16.row.col.f32.bf16.bf16.f32 "
                 "{%0,%1,%2,%3},{%4,%5,%6,%7},{%8,%9},{%0,%1,%2,%3};"
                 : "+f"(c[0]), "+f"(c[1]), "+f"(c[2]), "+f"(c[3])
                 : "r"(a[0]), "r"(a[1]), "r"(a[2]), "r"(a[3]), "r"(b[0]), "r"(b[1]));
}
__device__ __forceinline__ uint32_t packbf(float lo, float hi) {
    uint32_t r; asm("cvt.rn.bf16x2.f32 %0, %1, %2;" : "=r"(r) : "f"(hi), "f"(lo)); return r;
}

__device__ __forceinline__ float fexp(float x) {
    x = fmaxf(x, -80.f);
    float y = x * 1.442695041f;
    float n = rintf(y);
    float f = y - n;
    float p =            1.8775767e-3f;
    p = fmaf(p, f, 8.9893397e-3f);
    p = fmaf(p, f, 5.5826318e-2f);
    p = fmaf(p, f, 2.4015361e-1f);
    p = fmaf(p, f, 6.9315308e-1f);
    p = fmaf(p, f, 9.9999994e-1f);
    return __int_as_float(__float_as_int(p) + ((int)n << 23));
}
__device__ __forceinline__ float ftanh(float x) {
    float ax = fabsf(x);
    float e = fexp(-2.f * ax);
    float d = 1.f + e;
    float r = fmaf(-0.5f, d, 1.4571f);
    r = r * fmaf(-d, r, 2.f);
    r = r * fmaf(-d, r, 2.f);
    r = r * fmaf(-d, r, 2.f);
    float t = (1.f - e) * r;
    return (x >= 0.f) ? t : -t;
}
__device__ __forceinline__ void split3(__nv_bfloat16* p, float v) {
    __nv_bfloat16 hi = __float2bfloat16(v);
    __nv_bfloat16 lo = __float2bfloat16(v - __bfloat162float(hi));
    p[0] = hi; p[Dm] = hi; p[2*Dm] = lo;
}

// -------- fused prep: weight packs + rope tables + transpose-fused alignment --------
#define NB_WQKV 28224
#define NB_WO   9408
#define NB_ROPE 128
__global__ void prep_kernel(const float* __restrict__ Wq, const float* __restrict__ Wk,
                            const float* __restrict__ Wv, const float* __restrict__ Wo,
                            const float* __restrict__ bear, const float* __restrict__ wd,
                            __nv_bfloat16* __restrict__ wqkv, __nv_bfloat16* __restrict__ wocat,
                            float* __restrict__ cc, float* __restrict__ ss,
                            float* __restrict__ al)
{
    int bid = blockIdx.x, tid = threadIdx.x;
    if (bid < NB_WQKV) {
        size_t idx = (size_t)bid * 256 + tid;
        int k = (int)(idx % KCAT), n = (int)(idx / KCAT);
        const float* W = (n < Dm) ? Wq : ((n < 2*Dm) ? Wk : Wv);
        int c = n % Dm, kr = k % Dm, blk = k / Dm;
        float w = W[(size_t)kr * Dm + c];
        __nv_bfloat16 hi = __float2bfloat16(w);
        wqkv[idx] = (blk == 1) ? __float2bfloat16(w - __bfloat162float(hi)) : hi;
    } else if (bid < NB_WQKV + NB_WO) {
        size_t idx = (size_t)(bid - NB_WQKV) * 256 + tid;
        int k = (int)(idx % KCAT), n = (int)(idx / KCAT);
        int kr = k % Dm, blk = k / Dm;
        float w = Wo[(size_t)kr * Dm + n];
        __nv_bfloat16 hi = __float2bfloat16(w);
        wocat[idx] = (blk == 1) ? __float2bfloat16(w - __bfloat162float(hi)) : hi;
    } else if (bid < NB_WQKV + NB_WO + NB_ROPE) {
        int i = (bid - NB_WQKV - NB_WO) * 256 + tid;
        int n = i >> 5, d = i & 31;
        float freq = (float)n * powf(10000.f, -(float)(2*d) / 64.f);
        cc[i] = cosf(freq);
        ss[i] = sinf(freq);
    } else {
        int t = bid - NB_WQKV - NB_WO - NB_ROPE;       // 1024 blocks: 32x32 (q,k) tiles
        int q0 = (t >> 5) * 32, k0 = (t & 31) * 32;
        __shared__ float tile[32][33];
        int j = tid & 31, i = tid >> 5;
        #pragma unroll
        for (int p = 0; p < 4; p++)
            tile[i + p*8][j] = bear[(size_t)(k0 + i + p*8) * Nn + q0 + j];
        __syncthreads();
        #pragma unroll
        for (int p = 0; p < 4; p++) {
            int qi = i + p*8;
            float rb = fmodf(tile[j][qi] + 180.f, 360.f);
            #pragma unroll
            for (int b = 0; b < Bq; b++) {
                float a = (wd[b*Nn + q0 + qi] - rb) * 0.017453292519943295f;
                al[((size_t)b << 20) + (size_t)(q0 + qi) * Nn + k0 + j] = cosf(a);
            }
        }
    }
}

// -------------------- LayerNorm + split-pack --------------------
__global__ void ln_split_kernel(const float* __restrict__ x, const float* __restrict__ g,
                                const float* __restrict__ bb, __nv_bfloat16* __restrict__ y)
{
    int row = blockIdx.x;
    const float* xr = x + (size_t)row * Dm;
    float s = 0.f, s2 = 0.f;
    for (int i = threadIdx.x; i < Dm; i += 256) { float v = xr[i]; s += v; s2 += v*v; }
    #pragma unroll
    for (int o = 16; o; o >>= 1) { s += __shfl_xor_sync(~0u, s, o); s2 += __shfl_xor_sync(~0u, s2, o); }
    __shared__ float ws[8], ws2[8];
    int w = threadIdx.x >> 5;
    if ((threadIdx.x & 31) == 0) { ws[w] = s; ws2[w] = s2; }
    __syncthreads();
    if (threadIdx.x < 32) {
        s  = (threadIdx.x < 8) ? ws[threadIdx.x]  : 0.f;
        s2 = (threadIdx.x < 8) ? ws2[threadIdx.x] : 0.f;
        #pragma unroll
        for (int o = 4; o; o >>= 1) { s += __shfl_xor_sync(~0u, s, o); s2 += __shfl_xor_sync(~0u, s2, o); }
        if (threadIdx.x == 0) { ws[0] = s; ws2[0] = s2; }
    }
    __syncthreads();
    float mu  = ws[0] * (1.f/Dm);
    float var = ws2[0] * (1.f/Dm) - mu*mu;
    float inv = rsqrtf(var + 1e-5f);
    __nv_bfloat16* yr = y + (size_t)row * KCAT;
    for (int i = threadIdx.x; i < Dm; i += 256) {
        float v = (xr[i] - mu) * inv * g[i] + bb[i];
        split3(yr + i, v);
    }
}

// -------------------- gemm stage loader --------------------
__device__ __forceinline__ void load_stage(uint32_t abase, uint32_t bbase,
                                           const __nv_bfloat16* __restrict__ A,
                                           const __nv_bfloat16* __restrict__ Bw,
                                           int m0, int n0, int k0)
{
    int tid = threadIdx.x;
    #pragma unroll
    for (int p = 0; p < 2; p++) {
        int e = p * 256 + tid;
        int r = e >> 2, seg = e & 3;
        cp_async16(abase + r * 80 + seg * 16, A + (size_t)(m0 + r) * KCAT + k0 + seg * 8);
    }
    #pragma unroll
    for (int p = 0; p < 2; p++) {
        int e = p * 256 + tid;
        int r = e >> 2, seg = e & 3;
        cp_async16(bbase + r * 80 + seg * 16, Bw + (size_t)(n0 + r) * KCAT + k0 + seg * 8);
    }
}

// -------- mma GEMM. MODE0: QKV -> bf16 [hi|lo] rows + RoPE. MODE1: O-proj + residual --------
template<int MODE>
__global__ void __launch_bounds__(256, 2)
gemm_mma(const __nv_bfloat16* __restrict__ A, const __nv_bfloat16* __restrict__ Bw,
         const float* __restrict__ cosp, const float* __restrict__ sinp,
         const float* __restrict__ res, void* outQ, void* outK, void* outV)
{
    extern __shared__ char dsm[];
    uint32_t sb = smem_u32(dsm);
    float* sep = (float*)dsm;

    int tid = threadIdx.x, wid = tid >> 5, lane = tid & 31;
    int wm = wid >> 2, wn = wid & 3;
    int m0 = blockIdx.y * 128, n0 = blockIdx.x * 128;

    float acc[4][4][4];
    #pragma unroll
    for (int i = 0; i < 4; i++)
        #pragma unroll
        for (int j = 0; j < 4; j++)
            #pragma unroll
            for (int r = 0; r < 4; r++) acc[i][j][r] = 0.f;

    int gq = lane >> 3, lr = lane & 7;
    uint32_t a_off = (uint32_t)((wm*64 + lr + (gq & 1)*8) * 80 + (gq >> 1)*16);
    uint32_t b_off = (uint32_t)((wn*32 + lr) * 80 + ((lane & 8) ? 16 : 0));

    load_stage(sb + 0*STG, sb + 0*STG + 10240, A, Bw, m0, n0, 0);
    CP_COMMIT();
    load_stage(sb + 1*STG, sb + 1*STG + 10240, A, Bw, m0, n0, 32);
    CP_COMMIT();

    const int NT = KCAT / 32;
    int slot = 0;
    for (int i = 0; i < NT; i++) {
        if (i + 1 < NT) CP_WAIT1(); else CP_WAIT0();
        __syncthreads();
        uint32_t ab = sb + slot * STG, bb = ab + 10240;
        #pragma unroll
        for (int ks = 0; ks < 2; ks++) {
            uint32_t afr[4][4], bfr[4][2];
            #pragma unroll
            for (int mt = 0; mt < 4; mt++) ldsm_x4(ab + a_off + mt*(16*80) + ks*32, afr[mt]);
            #pragma unroll
            for (int nt = 0; nt < 4; nt++) ldsm_x2(bb + b_off + nt*(8*80) + ks*32, bfr[nt]);
            #pragma unroll
            for (int mt = 0; mt < 4; mt++)
                #pragma unroll
                for (int nt = 0; nt < 4; nt++)
                    mma16816(acc[mt][nt], afr[mt], bfr[nt]);
        }
        if (i + 2 < NT) {
            int ns = slot + 2; if (ns >= 3) ns -= 3;
            uint32_t nb = sb + ns * STG;
            load_stage(nb, nb + 10240, A, Bw, m0, n0, (i + 2) * 32);
            CP_COMMIT();
        }
        slot++; if (slot == 3) slot = 0;
    }
    __syncthreads();

    #pragma unroll
    for (int half = 0; half < 2; half++) {
        if (wm == half) {
            #pragma unroll
            for (int mt = 0; mt < 4; mt++)
                #pragma unroll
                for (int nt = 0; nt < 4; nt++)
                    #pragma unroll
                    for (int ri = 0; ri < 4; ri++) {
                        int r = mt*16 + (lane >> 2) + ((ri >> 1) * 8);
                        int n = wn*32 + nt*8 + ((lane & 3) * 2) + (ri & 1);
                        sep[r * EPITCH + n] = acc[mt][nt][ri];
                    }
        }
        __syncthreads();

        if (MODE == 0) {
            int tile = blockIdx.x;
            int region = tile / 7;
            int cbase = (tile % 7) * 128;
            __nv_bfloat16* base = (region == 0) ? (__nv_bfloat16*)outQ
                                : (region == 1) ? (__nv_bfloat16*)outK
                                                : (__nv_bfloat16*)outV;
            for (int idx = tid; idx < 64*128; idx += 256) {
                int r = idx >> 7, c = idx & 127;
                int m = m0 + half*64 + r;
                int bqi = m >> 10, n = m & 1023;
                int ccx = cbase + c;
                int head = ccx >> 6, d = ccx & 63;
                float val;
                if (region < 2) {
                    if (d < 32) {
                        float x1 = sep[r*EPITCH + c], x2 = sep[r*EPITCH + c + 32];
                        val = x1 * cosp[n*32 + d] - x2 * sinp[n*32 + d];
                    } else {
                        float x2 = sep[r*EPITCH + c], x1 = sep[r*EPITCH + c - 32];
                        int dd = d - 32;
                        val = x2 * cosp[n*32 + dd] + x1 * sinp[n*32 + dd];
                    }
                } else {
                    val = sep[r*EPITCH + c];
                }
                __nv_bfloat16 hv = __float2bfloat16(val);
                __nv_bfloat16 lv = __float2bfloat16(val - __bfloat162float(hv));
                size_t row = ((size_t)bqi * Hh + head) * Nn + n;
                base[row*128 + d]      = hv;
                base[row*128 + 64 + d] = lv;
            }
        } else {
            float* outp = (float*)outQ;
            for (int idx = tid; idx < 64*128; idx += 256) {
                int r = idx >> 7, c = idx & 127;
                int m = m0 + half*64 + r;
                size_t o = (size_t)m * Dm + n0 + c;
                outp[o] = sep[r*EPITCH + c] + res[o];
            }
        }
        __syncthreads();
    }
}

// -------- attn chunk loader: 256 rows x 256B, pitch 272 --------
__device__ __forceinline__ void ld_chunk(uint32_t dst, const __nv_bfloat16* __restrict__ src,
                                         int tok0)
{
    #pragma unroll
    for (int p = 0; p < 8; p++) {
        int e = p * 512 + threadIdx.x;
        int r = e >> 4, s = e & 15;
        cp_async16(dst + r * 272 + s * 16, src + (size_t)(tok0 + r) * 128 + s * 8);
    }
}
__device__ __forceinline__ void pfrag_pair(const float* sc, int r, int c,
                                           uint32_t& phi, uint32_t& plo)
{
    float2 p = *(const float2*)(sc + r * SCP + c);
    float h0 = __bfloat162float(__float2bfloat16(p.x));
    float h1 = __bfloat162float(__float2bfloat16(p.y));
    phi = packbf(p.x, p.y);
    plo = packbf(p.x - h0, p.y - h1);
}

// -------- mma attention: block (b,h,16q), 512 threads --------
__global__ void __launch_bounds__(512, 1)
attn_mma(const __nv_bfloat16* __restrict__ Qc, const __nv_bfloat16* __restrict__ Kc,
         const __nv_bfloat16* __restrict__ Vc, const float* __restrict__ adj,
         const float* __restrict__ al, const float* __restrict__ ww,
         const float* __restrict__ wbv, __nv_bfloat16* __restrict__ out)
{
    extern __shared__ char dsm[];
    float* sc = (float*)dsm;                       // [16][SCP] f32
    const int SCB = 16 * SCP * 4;
    uint32_t sb = smem_u32(dsm);
    uint32_t qs = sb + SCB;                        // Q tile 16 x 272
    uint32_t bu0 = qs + 16*272;
    uint32_t bu1 = bu0 + 256*272;
    float* part = (float*)(dsm + SCB + 16*272);    // overlays bu0 after PV

    int tid = threadIdx.x, wid = tid >> 5, lane = tid & 31;
    int h = blockIdx.y, b = blockIdx.z;
    int q0 = blockIdx.x * 16;
    size_t bh = ((size_t)b * Hh + h) * Nn;
    const __nv_bfloat16* Kbh = Kc + bh * 128;
    const __nv_bfloat16* Vbh = Vc + bh * 128;

    if (tid < 256) {
        int r = tid >> 4, s = tid & 15;
        cp_async16(qs + r*272 + s*16, Qc + (bh + q0 + r) * 128 + s * 8);
    }
    CP_COMMIT();
    ld_chunk(bu0, Kbh, 0);   CP_COMMIT();
    ld_chunk(bu1, Kbh, 256); CP_COMMIT();

    // ---- scores: S = qhi.khi + qhi.klo + qlo.khi ----
    {
        uint32_t afr[8][4];
        int gq = lane >> 3, lr = lane & 7;
        uint32_t a_off = qs + (uint32_t)((lr + (gq & 1)*8) * 272 + (gq >> 1)*16);
        for (int c = 0; c < 4; c++) {
            if (c < 3) CP_WAIT1(); else CP_WAIT0();
            __syncthreads();
            if (c == 0) {
                #pragma unroll
                for (int kt = 0; kt < 8; kt++) ldsm_x4(a_off + kt*32, afr[kt]);
            }
            uint32_t kb = (c & 1) ? bu1 : bu0;
            int tokb = c * 256 + wid * 16;
            uint32_t bbw = kb + (uint32_t)((wid*16 + (lane & 7)) * 272 + ((lane >> 3) & 1) * 16);
            #pragma unroll
            for (int nt = 0; nt < 2; nt++) {
                uint32_t bf[8][2];
                #pragma unroll
                for (int j = 0; j < 8; j++) ldsm_x2(bbw + (uint32_t)(nt*8*272) + j*32, bf[j]);
                float dd[4] = {0.f, 0.f, 0.f, 0.f};
                #pragma unroll
                for (int t = 0; t < 4; t++) mma16816(dd, afr[t],   bf[t]);
                #pragma unroll
                for (int t = 0; t < 4; t++) mma16816(dd, afr[t],   bf[4+t]);
                #pragma unroll
                for (int t = 0; t < 4; t++) mma16816(dd, afr[4+t], bf[t]);
                int col = tokb + nt*8 + 2*(lane & 3);
                int r = lane >> 2;
                *(float2*)(sc + r*SCP + col)     = make_float2(dd[0], dd[1]);
                *(float2*)(sc + (r+8)*SCP + col) = make_float2(dd[2], dd[3]);
            }
            __syncthreads();
            if (c + 2 < 4) { ld_chunk((c & 1) ? bu1 : bu0, Kbh, (c + 2) * 256); CP_COMMIT(); }
        }
    }

    // prefetch V (K buffers are free)
    ld_chunk(bu0, Vbh, 0);   CP_COMMIT();
    ld_chunk(bu1, Vbh, 256); CP_COMMIT();

    // ---- bias + mask ----
    {
        float w0 = ww[h], w1 = ww[Hh + h], wbias = wbv[h];
        for (int e = tid; e < 16*1024; e += 512) {
            int qi = e >> 10, k = e & 1023;
            float a  = adj[(size_t)(q0 + qi) * Nn + k];
            float av = al[((size_t)b << 20) + (size_t)(q0 + qi) * Nn + k];
            float bias = ftanh(av * w0 + a * w1 + wbias);
            float s = sc[qi * SCP + k];
            sc[qi * SCP + k] = (a > 0.f) ? fmaf(s, 0.125f, bias) : -1e30f;
        }
    }
    __syncthreads();

    // ---- softmax (warp per row), normalize inline ----
    {
        float* row = sc + wid * SCP;
        float mx = -1e30f;
        for (int k = lane; k < 1024; k += 32) mx = fmaxf(mx, row[k]);
        #pragma unroll
        for (int o = 16; o; o >>= 1) mx = fmaxf(mx, __shfl_xor_sync(~0u, mx, o));
        float sm = 0.f;
        for (int k = lane; k < 1024; k += 32) {
            float e = fexp(row[k] - mx);
            row[k] = e;
            sm += e;
        }
        #pragma unroll
        for (int o = 16; o; o >>= 1) sm += __shfl_xor_sync(~0u, sm, o);
        float inv = 1.f / sm;
        for (int k = lane; k < 1024; k += 32) row[k] *= inv;
    }
    __syncthreads();

    // ---- PV: D = phi.vhi + phi.vlo + plo.vhi, k split across 16 warps ----
    float acc[8][4];
    #pragma unroll
    for (int nt = 0; nt < 8; nt++)
        #pragma unroll
        for (int r = 0; r < 4; r++) acc[nt][r] = 0.f;

    for (int c = 0; c < 4; c++) {
        if (c < 3) CP_WAIT1(); else CP_WAIT0();
        __syncthreads();
        uint32_t vb = (c & 1) ? bu1 : bu0;
        int tokb = c * 256 + wid * 16;

        uint32_t phi[4], plo[4];
        {
            int r = lane >> 2, cb = tokb + 2*(lane & 3);
            pfrag_pair(sc, r,     cb,     phi[0], plo[0]);
            pfrag_pair(sc, r + 8, cb,     phi[1], plo[1]);
            pfrag_pair(sc, r,     cb + 8, phi[2], plo[2]);
            pfrag_pair(sc, r + 8, cb + 8, phi[3], plo[3]);
        }
        uint32_t vaddr = vb + (uint32_t)((wid*16 + ((lane >> 3) & 1)*8 + (lane & 7)) * 272
                                         + ((lane >> 4) & 1) * 16);
        uint32_t vfh[8][2], vfl[8][2];
        #pragma unroll
        for (int p = 0; p < 4; p++) {
            uint32_t r4[4];
            ldsm_x4t(vaddr + p*32, r4);
            vfh[2*p][0] = r4[0]; vfh[2*p][1] = r4[1];
            vfh[2*p+1][0] = r4[2]; vfh[2*p+1][1] = r4[3];
            ldsm_x4t(vaddr + 128 + p*32, r4);
            vfl[2*p][0] = r4[0]; vfl[2*p][1] = r4[1];
            vfl[2*p+1][0] = r4[2]; vfl[2*p+1][1] = r4[3];
        }
        #pragma unroll
        for (int nt = 0; nt < 8; nt++) {
            mma16816(acc[nt], phi, vfh[nt]);
            mma16816(acc[nt], phi, vfl[nt]);
            mma16816(acc[nt], plo, vfh[nt]);
        }
        __syncthreads();
        if (c + 2 < 4) { ld_chunk(vb, Vbh, (c + 2) * 256); CP_COMMIT(); }
    }

    // ---- cross-warp reduction ----
    {
        int r = lane >> 2, cc2 = 2*(lane & 3);
        #pragma unroll
        for (int nt = 0; nt < 8; nt++) {
            int d = nt*8 + cc2;
            *(float2*)(part + wid*1024 + r*64 + d)     = make_float2(acc[nt][0], acc[nt][1]);
            *(float2*)(part + wid*1024 + (r+8)*64 + d) = make_float2(acc[nt][2], acc[nt][3]);
        }
    }
    __syncthreads();
    for (int o = tid; o < 1024; o += 512) {
        float s = 0.f;
        #pragma unroll
        for (int w = 0; w < 16; w++) s += part[w*1024 + o];
        int qi = o >> 6, d = o & 63;
        int col = h * 64 + d;
        split3(out + (size_t)(b * Nn + q0 + qi) * KCAT + col, s);
    }
}

// -------------------- launch --------------------
extern "C" void kernel_launch(void* const* d_in, const int* in_sizes, int n_in,
                              void* d_out, int out_size)
{
    const float* node = (const float*)d_in[0];
    const float* adj  = (const float*)d_in[1];
    const float* wd   = (const float*)d_in[2];
    const float* bear = (const float*)d_in[3];
    const float* Wq   = (const float*)d_in[4];
    const float* Wk   = (const float*)d_in[5];
    const float* Wv   = (const float*)d_in[6];
    const float* Wo   = (const float*)d_in[7];
    const float* lng  = (const float*)d_in[8];
    const float* lnb  = (const float*)d_in[9];
    const float* ww   = (const float*)d_in[10];
    const float* wbv  = (const float*)d_in[11];
    float* out = (float*)d_out;

    __nv_bfloat16 *xcat, *wqkv, *wocat, *aocat, *Qc, *Kc, *Vc;
    float *alp, *cosp, *sinp;
    cudaGetSymbolAddress((void**)&xcat,  g_xcat);
    cudaGetSymbolAddress((void**)&wqkv,  g_wqkv);
    cudaGetSymbolAddress((void**)&wocat, g_wocat);
    cudaGetSymbolAddress((void**)&aocat, g_aocat);
    cudaGetSymbolAddress((void**)&Qc,    g_Qc);
    cudaGetSymbolAddress((void**)&Kc,    g_Kc);
    cudaGetSymbolAddress((void**)&Vc,    g_Vc);
    cudaGetSymbolAddress((void**)&alp,   g_align);
    cudaGetSymbolAddress((void**)&cosp,  g_cos);
    cudaGetSymbolAddress((void**)&sinp,  g_sin);

    const int SMEM_GEMM = 3 * STG;
    const int SMEM_ATTN = 16*SCP*4 + 16*272 + 2*256*272;   // 209664
    cudaFuncSetAttribute(gemm_mma<0>, cudaFuncAttributeMaxDynamicSharedMemorySize, SMEM_GEMM);
    cudaFuncSetAttribute(gemm_mma<1>, cudaFuncAttributeMaxDynamicSharedMemorySize, SMEM_GEMM);
    cudaFuncSetAttribute(attn_mma,    cudaFuncAttributeMaxDynamicSharedMemorySize, SMEM_ATTN);

    // 1: fused prep
    prep_kernel<<<NB_WQKV + NB_WO + NB_ROPE + 1024, 256>>>(Wq, Wk, Wv, Wo, bear, wd,
                                                           wqkv, wocat, cosp, sinp, alp);
    // 2: LN + split
    ln_split_kernel<<<BN, 256>>>(node, lng, lnb, xcat);
    // 3: fused QKV GEMM (RoPE + bf16 split rows in epilogue)
    gemm_mma<0><<<dim3(KCAT/128, BN/128), 256, SMEM_GEMM>>>(xcat, wqkv, cosp, sinp,
                                                            nullptr, Qc, Kc, Vc);
    // 4: mma attention (PROFILED)
    attn_mma<<<dim3(Nn/16, Hh, Bq), 512, SMEM_ATTN>>>(Qc, Kc, Vc, adj, alp, ww, wbv, aocat);
    // 5: O-proj + residual
    gemm_mma<1><<<dim3(Dm/128, BN/128), 256, SMEM_GEMM>>>(aocat, wocat, cosp, sinp,
                                                          node, out, nullptr, nullptr);
}

// round 8
// speedup vs baseline: 1.8696x; 1.5693x over previous
#include <cuda_runtime.h>
#include <cuda_bf16.h>
#include <math.h>
#include <stdint.h>

#define Bq   8
#define Nn   1024
#define Dm   896
#define Hh   14
#define Dh   64
#define BN   (Bq*Nn)
#define KCAT 2688
#define EPITCH 132
#define STG  20480
#define SCP  1032

__device__ __align__(128) __nv_bfloat16 g_xcat[(size_t)BN*KCAT];
__device__ __align__(128) __nv_bfloat16 g_wqkv[(size_t)KCAT*KCAT];
__device__ __align__(128) __nv_bfloat16 g_wocat[(size_t)Dm*KCAT];
__device__ __align__(128) __nv_bfloat16 g_aocat[(size_t)BN*KCAT];
__device__ __align__(128) __nv_bfloat16 g_Qc[(size_t)Bq*Hh*Nn*128];
__device__ __align__(128) __nv_bfloat16 g_Kc[(size_t)Bq*Hh*Nn*128];
__device__ __align__(128) __nv_bfloat16 g_Vc[(size_t)Bq*Hh*Nn*128];
__device__ float g_bias[(size_t)Bq*Hh*Nn*Nn];   // masked wind bias, f32
__device__ float g_cos[Nn*32];
__device__ float g_sin[Nn*32];

__device__ __forceinline__ uint32_t smem_u32(const void* p) {
    uint32_t a;
    asm("{ .reg .u64 t; cvta.to.shared.u64 t, %1; cvt.u32.u64 %0, t; }" : "=r"(a) : "l"(p));
    return a;
}
__device__ __forceinline__ void cp_async16(uint32_t dst, const void* src) {
    asm volatile("cp.async.cg.shared.global [%0], [%1], 16;" :: "r"(dst), "l"(src));
}
#define CP_COMMIT() asm volatile("cp.async.commit_group;" ::: "memory")
#define CP_WAIT0()  asm volatile("cp.async.wait_group 0;" ::: "memory")
#define CP_WAIT1()  asm volatile("cp.async.wait_group 1;" ::: "memory")

__device__ __forceinline__ void ldsm_x4(uint32_t a, uint32_t* r) {
    asm volatile("ldmatrix.sync.aligned.m8n8.x4.shared.b16 {%0,%1,%2,%3}, [%4];"
                 : "=r"(r[0]), "=r"(r[1]), "=r"(r[2]), "=r"(r[3]) : "r"(a));
}
__device__ __forceinline__ void ldsm_x2(uint32_t a, uint32_t* r) {
    asm volatile("ldmatrix.sync.aligned.m8n8.x2.shared.b16 {%0,%1}, [%2];"
                 : "=r"(r[0]), "=r"(r[1]) : "r"(a));
}
__device__ __forceinline__ void ldsm_x4t(uint32_t a, uint32_t* r) {
    asm volatile("ldmatrix.sync.aligned.m8n8.x4.trans.shared.b16 {%0,%1,%2,%3}, [%4];"
                 : "=r"(r[0]), "=r"(r[1]), "=r"(r[2]), "=r"(r[3]) : "r"(a));
}
__device__ __forceinline__ void mma16816(float* c, const uint32_t* a, const uint32_t* b) {
    asm volatile("mma.sync.aligned.m16n8k16.row.col.f32.bf16.bf16.f32 "
                 "{%0,%1,%2,%3},{%4,%5,%6,%7},{%8,%9},{%0,%1,%2,%3};"
                 : "+f"(c[0]), "+f"(c[1]), "+f"(c[2]), "+f"(c[3])
                 : "r"(a[0]), "r"(a[1]), "r"(a[2]), "r"(a[3]), "r"(b[0]), "r"(b[1]));
}
__device__ __forceinline__ uint32_t packbf(float lo, float hi) {
    uint32_t r; asm("cvt.rn.bf16x2.f32 %0, %1, %2;" : "=r"(r) : "f"(hi), "f"(lo)); return r;
}

__device__ __forceinline__ float fexp(float x) {
    x = fmaxf(x, -80.f);
    float y = x * 1.442695041f;
    float n = rintf(y);
    float f = y - n;
    float p =            1.8775767e-3f;
    p = fmaf(p, f, 8.9893397e-3f);
    p = fmaf(p, f, 5.5826318e-2f);
    p = fmaf(p, f, 2.4015361e-1f);
    p = fmaf(p, f, 6.9315308e-1f);
    p = fmaf(p, f, 9.9999994e-1f);
    return __int_as_float(__float_as_int(p) + ((int)n << 23));
}
__device__ __forceinline__ float ftanh(float x) {
    float ax = fabsf(x);
    float e = fexp(-2.f * ax);
    float d = 1.f + e;
    float r = fmaf(-0.5f, d, 1.4571f);
    r = r * fmaf(-d, r, 2.f);
    r = r * fmaf(-d, r, 2.f);
    r = r * fmaf(-d, r, 2.f);
    float t = (1.f - e) * r;
    return (x >= 0.f) ? t : -t;
}
__device__ __forceinline__ void split3(__nv_bfloat16* p, float v) {
    __nv_bfloat16 hi = __float2bfloat16(v);
    __nv_bfloat16 lo = __float2bfloat16(v - __bfloat162float(hi));
    p[0] = hi; p[Dm] = hi; p[2*Dm] = lo;
}

// -------- prep: weight packs + rope tables + layernorm(split) --------
#define NB_WQKV 28224
#define NB_WO   9408
#define NB_ROPE 128
__global__ void prep_kernel(const float* __restrict__ Wq, const float* __restrict__ Wk,
                            const float* __restrict__ Wv, const float* __restrict__ Wo,
                            const float* __restrict__ x, const float* __restrict__ lng,
                            const float* __restrict__ lnb,
                            __nv_bfloat16* __restrict__ wqkv, __nv_bfloat16* __restrict__ wocat,
                            float* __restrict__ cc, float* __restrict__ ss,
                            __nv_bfloat16* __restrict__ y)
{
    int bid = blockIdx.x, tid = threadIdx.x;
    if (bid < NB_WQKV) {
        size_t idx = (size_t)bid * 256 + tid;
        int k = (int)(idx % KCAT), n = (int)(idx / KCAT);
        const float* W = (n < Dm) ? Wq : ((n < 2*Dm) ? Wk : Wv);
        int c = n % Dm, kr = k % Dm, blk = k / Dm;
        float w = W[(size_t)kr * Dm + c];
        __nv_bfloat16 hi = __float2bfloat16(w);
        wqkv[idx] = (blk == 1) ? __float2bfloat16(w - __bfloat162float(hi)) : hi;
    } else if (bid < NB_WQKV + NB_WO) {
        size_t idx = (size_t)(bid - NB_WQKV) * 256 + tid;
        int k = (int)(idx % KCAT), n = (int)(idx / KCAT);
        int kr = k % Dm, blk = k / Dm;
        float w = Wo[(size_t)kr * Dm + n];
        __nv_bfloat16 hi = __float2bfloat16(w);
        wocat[idx] = (blk == 1) ? __float2bfloat16(w - __bfloat162float(hi)) : hi;
    } else if (bid < NB_WQKV + NB_WO + NB_ROPE) {
        int i = (bid - NB_WQKV - NB_WO) * 256 + tid;
        int n = i >> 5, d = i & 31;
        float freq = (float)n * powf(10000.f, -(float)(2*d) / 64.f);
        cc[i] = cosf(freq);
        ss[i] = sinf(freq);
    } else {
        // layernorm + split-pack, one row per block
        int row = bid - (NB_WQKV + NB_WO + NB_ROPE);
        const float* xr = x + (size_t)row * Dm;
        float s = 0.f, s2 = 0.f;
        for (int i = tid; i < Dm; i += 256) { float v = xr[i]; s += v; s2 += v*v; }
        #pragma unroll
        for (int o = 16; o; o >>= 1) { s += __shfl_xor_sync(~0u, s, o); s2 += __shfl_xor_sync(~0u, s2, o); }
        __shared__ float ws[8], ws2[8];
        int w = tid >> 5;
        if ((tid & 31) == 0) { ws[w] = s; ws2[w] = s2; }
        __syncthreads();
        if (tid < 32) {
            s  = (tid < 8) ? ws[tid]  : 0.f;
            s2 = (tid < 8) ? ws2[tid] : 0.f;
            #pragma unroll
            for (int o = 4; o; o >>= 1) { s += __shfl_xor_sync(~0u, s, o); s2 += __shfl_xor_sync(~0u, s2, o); }
            if (tid == 0) { ws[0] = s; ws2[0] = s2; }
        }
        __syncthreads();
        float mu  = ws[0] * (1.f/Dm);
        float var = ws2[0] * (1.f/Dm) - mu*mu;
        float inv = rsqrtf(var + 1e-5f);
        __nv_bfloat16* yr = y + (size_t)row * KCAT;
        for (int i = tid; i < Dm; i += 256) {
            float v = (xr[i] - mu) * inv * lng[i] + lnb[i];
            split3(yr + i, v);
        }
    }
}

// -------- bias precompute: masked tanh wind bias, all heads --------
__global__ void bias_kernel(const float* __restrict__ bear, const float* __restrict__ wd,
                            const float* __restrict__ adj, const float* __restrict__ ww,
                            const float* __restrict__ wbv, float* __restrict__ bias)
{
    int t = blockIdx.x;                 // 1024 tiles of 32x32 (q,k)
    int b = blockIdx.y;
    int q0 = (t >> 5) * 32, k0 = (t & 31) * 32;
    __shared__ float tile[32][33];
    __shared__ float w0s[Hh], w1s[Hh], wbs[Hh];
    int tid = threadIdx.x;
    int j = tid & 31, i = tid >> 5;
    if (tid < Hh) { w0s[tid] = ww[tid]; w1s[tid] = ww[Hh + tid]; wbs[tid] = wbv[tid]; }
    #pragma unroll
    for (int p = 0; p < 4; p++)
        tile[i + p*8][j] = bear[(size_t)(k0 + i + p*8) * Nn + q0 + j];
    __syncthreads();
    #pragma unroll
    for (int p = 0; p < 4; p++) {
        int qi = i + p*8;
        int q = q0 + qi, k = k0 + j;
        float rb = fmodf(tile[j][qi] + 180.f, 360.f);
        float av = cosf((wd[b*Nn + q] - rb) * 0.017453292519943295f);
        float a  = adj[(size_t)q * Nn + k];
        bool on = (a > 0.f);
        size_t base = ((size_t)q << 10) + k;
        #pragma unroll
        for (int h = 0; h < Hh; h++) {
            float bv = on ? ftanh(fmaf(av, w0s[h], fmaf(a, w1s[h], wbs[h]))) : -1e30f;
            bias[(((size_t)(b*Hh + h)) << 20) + base] = bv;
        }
    }
}

// -------- gemm stage loader --------
__device__ __forceinline__ void load_stage(uint32_t abase, uint32_t bbase,
                                           const __nv_bfloat16* __restrict__ A,
                                           const __nv_bfloat16* __restrict__ Bw,
                                           int m0, int n0, int k0)
{
    int tid = threadIdx.x;
    #pragma unroll
    for (int p = 0; p < 2; p++) {
        int e = p * 256 + tid;
        int r = e >> 2, seg = e & 3;
        cp_async16(abase + r * 80 + seg * 16, A + (size_t)(m0 + r) * KCAT + k0 + seg * 8);
    }
    #pragma unroll
    for (int p = 0; p < 2; p++) {
        int e = p * 256 + tid;
        int r = e >> 2, seg = e & 3;
        cp_async16(bbase + r * 80 + seg * 16, Bw + (size_t)(n0 + r) * KCAT + k0 + seg * 8);
    }
}

// -------- mma GEMM. MODE0: QKV -> bf16 [hi|lo] rows + RoPE. MODE1: O-proj + residual --------
template<int MODE>
__global__ void __launch_bounds__(256, 2)
gemm_mma(const __nv_bfloat16* __restrict__ A, const __nv_bfloat16* __restrict__ Bw,
         const float* __restrict__ cosp, const float* __restrict__ sinp,
         const float* __restrict__ res, void* outQ, void* outK, void* outV)
{
    extern __shared__ char dsm[];
    uint32_t sb = smem_u32(dsm);
    float* sep = (float*)dsm;

    int tid = threadIdx.x, wid = tid >> 5, lane = tid & 31;
    int wm = wid >> 2, wn = wid & 3;
    int m0 = blockIdx.y * 128, n0 = blockIdx.x * 128;

    float acc[4][4][4];
    #pragma unroll
    for (int i = 0; i < 4; i++)
        #pragma unroll
        for (int j = 0; j < 4; j++)
            #pragma unroll
            for (int r = 0; r < 4; r++) acc[i][j][r] = 0.f;

    int gq = lane >> 3, lr = lane & 7;
    uint32_t a_off = (uint32_t)((wm*64 + lr + (gq & 1)*8) * 80 + (gq >> 1)*16);
    uint32_t b_off = (uint32_t)((wn*32 + lr) * 80 + ((lane & 8) ? 16 : 0));

    load_stage(sb + 0*STG, sb + 0*STG + 10240, A, Bw, m0, n0, 0);
    CP_COMMIT();
    load_stage(sb + 1*STG, sb + 1*STG + 10240, A, Bw, m0, n0, 32);
    CP_COMMIT();

    const int NT = KCAT / 32;
    int slot = 0;
    for (int i = 0; i < NT; i++) {
        if (i + 1 < NT) CP_WAIT1(); else CP_WAIT0();
        __syncthreads();
        uint32_t ab = sb + slot * STG, bb = ab + 10240;
        #pragma unroll
        for (int ks = 0; ks < 2; ks++) {
            uint32_t afr[4][4], bfr[4][2];
            #pragma unroll
            for (int mt = 0; mt < 4; mt++) ldsm_x4(ab + a_off + mt*(16*80) + ks*32, afr[mt]);
            #pragma unroll
            for (int nt = 0; nt < 4; nt++) ldsm_x2(bb + b_off + nt*(8*80) + ks*32, bfr[nt]);
            #pragma unroll
            for (int mt = 0; mt < 4; mt++)
                #pragma unroll
                for (int nt = 0; nt < 4; nt++)
                    mma16816(acc[mt][nt], afr[mt], bfr[nt]);
        }
        if (i + 2 < NT) {
            int ns = slot + 2; if (ns >= 3) ns -= 3;
            uint32_t nb = sb + ns * STG;
            load_stage(nb, nb + 10240, A, Bw, m0, n0, (i + 2) * 32);
            CP_COMMIT();
        }
        slot++; if (slot == 3) slot = 0;
    }
    __syncthreads();

    #pragma unroll
    for (int half = 0; half < 2; half++) {
        if (wm == half) {
            #pragma unroll
            for (int mt = 0; mt < 4; mt++)
                #pragma unroll
                for (int nt = 0; nt < 4; nt++)
                    #pragma unroll
                    for (int ri = 0; ri < 4; ri++) {
                        int r = mt*16 + (lane >> 2) + ((ri >> 1) * 8);
                        int n = wn*32 + nt*8 + ((lane & 3) * 2) + (ri & 1);
                        sep[r * EPITCH + n] = acc[mt][nt][ri];
                    }
        }
        __syncthreads();

        if (MODE == 0) {
            int tile = blockIdx.x;
            int region = tile / 7;
            int cbase = (tile % 7) * 128;
            __nv_bfloat16* base = (region == 0) ? (__nv_bfloat16*)outQ
                                : (region == 1) ? (__nv_bfloat16*)outK
                                                : (__nv_bfloat16*)outV;
            for (int idx = tid; idx < 64*128; idx += 256) {
                int r = idx >> 7, c = idx & 127;
                int m = m0 + half*64 + r;
                int bqi = m >> 10, n = m & 1023;
                int ccx = cbase + c;
                int head = ccx >> 6, d = ccx & 63;
                float val;
                if (region < 2) {
                    if (d < 32) {
                        float x1 = sep[r*EPITCH + c], x2 = sep[r*EPITCH + c + 32];
                        val = x1 * cosp[n*32 + d] - x2 * sinp[n*32 + d];
                    } else {
                        float x2 = sep[r*EPITCH + c], x1 = sep[r*EPITCH + c - 32];
                        int dd = d - 32;
                        val = x2 * cosp[n*32 + dd] + x1 * sinp[n*32 + dd];
                    }
                } else {
                    val = sep[r*EPITCH + c];
                }
                __nv_bfloat16 hv = __float2bfloat16(val);
                __nv_bfloat16 lv = __float2bfloat16(val - __bfloat162float(hv));
                size_t row = ((size_t)bqi * Hh + head) * Nn + n;
                base[row*128 + d]      = hv;
                base[row*128 + 64 + d] = lv;
            }
        } else {
            float* outp = (float*)outQ;
            for (int idx = tid; idx < 64*128; idx += 256) {
                int r = idx >> 7, c = idx & 127;
                int m = m0 + half*64 + r;
                size_t o = (size_t)m * Dm + n0 + c;
                outp[o] = sep[r*EPITCH + c] + res[o];
            }
        }
        __syncthreads();
    }
}

// -------- attn chunk loader: 256 rows x 256B, pitch 272 --------
__device__ __forceinline__ void ld_chunk(uint32_t dst, const __nv_bfloat16* __restrict__ src,
                                         int tok0)
{
    #pragma unroll
    for (int p = 0; p < 8; p++) {
        int e = p * 512 + threadIdx.x;
        int r = e >> 4, s = e & 15;
        cp_async16(dst + r * 272 + s * 16, src + (size_t)(tok0 + r) * 128 + s * 8);
    }
}
__device__ __forceinline__ void pfrag_pair(const float* sc, int r, int c,
                                           uint32_t& phi, uint32_t& plo)
{
    float2 p = *(const float2*)(sc + r * SCP + c);
    float h0 = __bfloat162float(__float2bfloat16(p.x));
    float h1 = __bfloat162float(__float2bfloat16(p.y));
    phi = packbf(p.x, p.y);
    plo = packbf(p.x - h0, p.y - h1);
}

// -------- mma attention: block (b,h,16q), 512 threads; bias fused from gmem --------
__global__ void __launch_bounds__(512, 1)
attn_mma(const __nv_bfloat16* __restrict__ Qc, const __nv_bfloat16* __restrict__ Kc,
         const __nv_bfloat16* __restrict__ Vc, const float* __restrict__ bias,
         __nv_bfloat16* __restrict__ out)
{
    extern __shared__ char dsm[];
    float* sc = (float*)dsm;                       // [16][SCP] f32
    const int SCB = 16 * SCP * 4;
    uint32_t sb = smem_u32(dsm);
    uint32_t qs = sb + SCB;                        // Q tile 16 x 272
    uint32_t bu0 = qs + 16*272;
    uint32_t bu1 = bu0 + 256*272;
    float* part = (float*)(dsm + SCB + 16*272);    // overlays bu0 after PV

    int tid = threadIdx.x, wid = tid >> 5, lane = tid & 31;
    int h = blockIdx.y, b = blockIdx.z;
    int q0 = blockIdx.x * 16;
    size_t bh = ((size_t)b * Hh + h) * Nn;
    const __nv_bfloat16* Kbh = Kc + bh * 128;
    const __nv_bfloat16* Vbh = Vc + bh * 128;
    const float* biasbh = bias + (((size_t)(b*Hh + h)) << 20);

    if (tid < 256) {
        int r = tid >> 4, s = tid & 15;
        cp_async16(qs + r*272 + s*16, Qc + (bh + q0 + r) * 128 + s * 8);
    }
    CP_COMMIT();
    ld_chunk(bu0, Kbh, 0);   CP_COMMIT();
    ld_chunk(bu1, Kbh, 256); CP_COMMIT();

    // ---- scores: S = (qhi.khi + qhi.klo + qlo.khi)*0.125 + bias ----
    {
        uint32_t afr[8][4];
        int gq = lane >> 3, lr = lane & 7;
        uint32_t a_off = qs + (uint32_t)((lr + (gq & 1)*8) * 272 + (gq >> 1)*16);
        for (int c = 0; c < 4; c++) {
            if (c < 3) CP_WAIT1(); else CP_WAIT0();
            __syncthreads();
            if (c == 0) {
                #pragma unroll
                for (int kt = 0; kt < 8; kt++) ldsm_x4(a_off + kt*32, afr[kt]);
            }
            uint32_t kb = (c & 1) ? bu1 : bu0;
            int tokb = c * 256 + wid * 16;
            uint32_t bbw = kb + (uint32_t)((wid*16 + (lane & 7)) * 272 + ((lane >> 3) & 1) * 16);
            #pragma unroll
            for (int nt = 0; nt < 2; nt++) {
                uint32_t bf[8][2];
                #pragma unroll
                for (int j = 0; j < 8; j++) ldsm_x2(bbw + (uint32_t)(nt*8*272) + j*32, bf[j]);
                float dd[4] = {0.f, 0.f, 0.f, 0.f};
                #pragma unroll
                for (int t = 0; t < 4; t++) mma16816(dd, afr[t],   bf[t]);
                #pragma unroll
                for (int t = 0; t < 4; t++) mma16816(dd, afr[t],   bf[4+t]);
                #pragma unroll
                for (int t = 0; t < 4; t++) mma16816(dd, afr[4+t], bf[t]);
                int col = tokb + nt*8 + 2*(lane & 3);
                int r = lane >> 2;
                const float* br0 = biasbh + (((size_t)(q0 + r))     << 10) + col;
                const float* br1 = biasbh + (((size_t)(q0 + r + 8)) << 10) + col;
                float2 b0 = *(const float2*)br0;
                float2 b1 = *(const float2*)br1;
                *(float2*)(sc + r*SCP + col) =
                    make_float2(fmaf(dd[0], 0.125f, b0.x), fmaf(dd[1], 0.125f, b0.y));
                *(float2*)(sc + (r+8)*SCP + col) =
                    make_float2(fmaf(dd[2], 0.125f, b1.x), fmaf(dd[3], 0.125f, b1.y));
            }
            __syncthreads();
            if (c + 2 < 4) { ld_chunk((c & 1) ? bu1 : bu0, Kbh, (c + 2) * 256); CP_COMMIT(); }
        }
    }

    // prefetch V (K buffers free)
    ld_chunk(bu0, Vbh, 0);   CP_COMMIT();
    ld_chunk(bu1, Vbh, 256); CP_COMMIT();

    // ---- softmax (warp per row), normalize inline ----
    {
        float* row = sc + wid * SCP;
        float mx = -1e30f;
        for (int k = lane; k < 1024; k += 32) mx = fmaxf(mx, row[k]);
        #pragma unroll
        for (int o = 16; o; o >>= 1) mx = fmaxf(mx, __shfl_xor_sync(~0u, mx, o));
        float sm = 0.f;
        for (int k = lane; k < 1024; k += 32) {
            float e = fexp(row[k] - mx);
            row[k] = e;
            sm += e;
        }
        #pragma unroll
        for (int o = 16; o; o >>= 1) sm += __shfl_xor_sync(~0u, sm, o);
        float inv = 1.f / sm;
        for (int k = lane; k < 1024; k += 32) row[k] *= inv;
    }
    __syncthreads();

    // ---- PV: D = phi.vhi + phi.vlo + plo.vhi, k split across 16 warps ----
    float acc[8][4];
    #pragma unroll
    for (int nt = 0; nt < 8; nt++)
        #pragma unroll
        for (int r = 0; r < 4; r++) acc[nt][r] = 0.f;

    for (int c = 0; c < 4; c++) {
        if (c < 3) CP_WAIT1(); else CP_WAIT0();
        __syncthreads();
        uint32_t vb = (c & 1) ? bu1 : bu0;
        int tokb = c * 256 + wid * 16;

        uint32_t phi[4], plo[4];
        {
            int r = lane >> 2, cb = tokb + 2*(lane & 3);
            pfrag_pair(sc, r,     cb,     phi[0], plo[0]);
            pfrag_pair(sc, r + 8, cb,     phi[1], plo[1]);
            pfrag_pair(sc, r,     cb + 8, phi[2], plo[2]);
            pfrag_pair(sc, r + 8, cb + 8, phi[3], plo[3]);
        }
        uint32_t vaddr = vb + (uint32_t)((wid*16 + ((lane >> 3) & 1)*8 + (lane & 7)) * 272
                                         + ((lane >> 4) & 1) * 16);
        uint32_t vfh[8][2], vfl[8][2];
        #pragma unroll
        for (int p = 0; p < 4; p++) {
            uint32_t r4[4];
            ldsm_x4t(vaddr + p*32, r4);
            vfh[2*p][0] = r4[0]; vfh[2*p][1] = r4[1];
            vfh[2*p+1][0] = r4[2]; vfh[2*p+1][1] = r4[3];
            ldsm_x4t(vaddr + 128 + p*32, r4);
            vfl[2*p][0] = r4[0]; vfl[2*p][1] = r4[1];
            vfl[2*p+1][0] = r4[2]; vfl[2*p+1][1] = r4[3];
        }
        #pragma unroll
        for (int nt = 0; nt < 8; nt++) {
            mma16816(acc[nt], phi, vfh[nt]);
            mma16816(acc[nt], phi, vfl[nt]);
            mma16816(acc[nt], plo, vfh[nt]);
        }
        __syncthreads();
        if (c + 2 < 4) { ld_chunk(vb, Vbh, (c + 2) * 256); CP_COMMIT(); }
    }

    // ---- cross-warp reduction ----
    {
        int r = lane >> 2, cc2 = 2*(lane & 3);
        #pragma unroll
        for (int nt = 0; nt < 8; nt++) {
            int d = nt*8 + cc2;
            *(float2*)(part + wid*1024 + r*64 + d)     = make_float2(acc[nt][0], acc[nt][1]);
            *(float2*)(part + wid*1024 + (r+8)*64 + d) = make_float2(acc[nt][2], acc[nt][3]);
        }
    }
    __syncthreads();
    for (int o = tid; o < 1024; o += 512) {
        float s = 0.f;
        #pragma unroll
        for (int w = 0; w < 16; w++) s += part[w*1024 + o];
        int qi = o >> 6, d = o & 63;
        int col = h * 64 + d;
        split3(out + (size_t)(b * Nn + q0 + qi) * KCAT + col, s);
    }
}

// -------------------- launch --------------------
extern "C" void kernel_launch(void* const* d_in, const int* in_sizes, int n_in,
                              void* d_out, int out_size)
{
    const float* node = (const float*)d_in[0];
    const float* adj  = (const float*)d_in[1];
    const float* wd   = (const float*)d_in[2];
    const float* bear = (const float*)d_in[3];
    const float* Wq   = (const float*)d_in[4];
    const float* Wk   = (const float*)d_in[5];
    const float* Wv   = (const float*)d_in[6];
    const float* Wo   = (const float*)d_in[7];
    const float* lng  = (const float*)d_in[8];
    const float* lnb  = (const float*)d_in[9];
    const float* ww   = (const float*)d_in[10];
    const float* wbv  = (const float*)d_in[11];
    float* out = (float*)d_out;

    __nv_bfloat16 *xcat, *wqkv, *wocat, *aocat, *Qc, *Kc, *Vc;
    float *biasp, *cosp, *sinp;
    cudaGetSymbolAddress((void**)&xcat,  g_xcat);
    cudaGetSymbolAddress((void**)&wqkv,  g_wqkv);
    cudaGetSymbolAddress((void**)&wocat, g_wocat);
    cudaGetSymbolAddress((void**)&aocat, g_aocat);
    cudaGetSymbolAddress((void**)&Qc,    g_Qc);
    cudaGetSymbolAddress((void**)&Kc,    g_Kc);
    cudaGetSymbolAddress((void**)&Vc,    g_Vc);
    cudaGetSymbolAddress((void**)&biasp, g_bias);
    cudaGetSymbolAddress((void**)&cosp,  g_cos);
    cudaGetSymbolAddress((void**)&sinp,  g_sin);

    const int SMEM_GEMM = 3 * STG;
    const int SMEM_ATTN = 16*SCP*4 + 16*272 + 2*256*272;   // 209664
    cudaFuncSetAttribute(gemm_mma<0>, cudaFuncAttributeMaxDynamicSharedMemorySize, SMEM_GEMM);
    cudaFuncSetAttribute(gemm_mma<1>, cudaFuncAttributeMaxDynamicSharedMemorySize, SMEM_GEMM);
    cudaFuncSetAttribute(attn_mma,    cudaFuncAttributeMaxDynamicSharedMemorySize, SMEM_ATTN);

    // 1: prep (weights + rope + layernorm)
    prep_kernel<<<NB_WQKV + NB_WO + NB_ROPE + BN, 256>>>(Wq, Wk, Wv, Wo, node, lng, lnb,
                                                         wqkv, wocat, cosp, sinp, xcat);
    // 2: masked wind-bias precompute (all heads)
    bias_kernel<<<dim3(1024, Bq), 256>>>(bear, wd, adj, ww, wbv, biasp);
    // 3: fused QKV GEMM (RoPE + bf16 split rows in epilogue)
    gemm_mma<0><<<dim3(KCAT/128, BN/128), 256, SMEM_GEMM>>>(xcat, wqkv, cosp, sinp,
                                                            nullptr, Qc, Kc, Vc);
    // 4: mma attention (PROFILED)
    attn_mma<<<dim3(Nn/16, Hh, Bq), 512, SMEM_ATTN>>>(Qc, Kc, Vc, biasp, aocat);
    // 5: O-proj + residual
    gemm_mma<1><<<dim3(Dm/128, BN/128), 256, SMEM_GEMM>>>(aocat, wocat, cosp, sinp,
                                                          node, out, nullptr, nullptr);
}

// round 9
// speedup vs baseline: 2.0545x; 1.0989x over previous
#include <cuda_runtime.h>
#include <cuda_bf16.h>
#include <math.h>
#include <stdint.h>

#define Bq   8
#define Nn   1024
#define Dm   896
#define Hh   14
#define Dh   64
#define BN   (Bq*Nn)
#define KCAT 2688
#define EPITCH 132
#define STG  20480
#define SCP  1032
#define NCH  16          // attn chunks (64 tokens each)

__device__ __align__(128) __nv_bfloat16 g_xcat[(size_t)BN*KCAT];
__device__ __align__(128) __nv_bfloat16 g_wqkv[(size_t)KCAT*KCAT];
__device__ __align__(128) __nv_bfloat16 g_wocat[(size_t)Dm*KCAT];
__device__ __align__(128) __nv_bfloat16 g_aocat[(size_t)BN*KCAT];
__device__ __align__(128) __nv_bfloat16 g_Qc[(size_t)Bq*Hh*Nn*128];
__device__ __align__(128) __nv_bfloat16 g_Kc[(size_t)Bq*Hh*Nn*128];
__device__ __align__(128) __nv_bfloat16 g_Vc[(size_t)Bq*Hh*Nn*128];
__device__ float g_bias[(size_t)Bq*Hh*Nn*Nn];
__device__ float g_cos[Nn*32];
__device__ float g_sin[Nn*32];

__device__ __forceinline__ uint32_t smem_u32(const void* p) {
    uint32_t a;
    asm("{ .reg .u64 t; cvta.to.shared.u64 t, %1; cvt.u32.u64 %0, t; }" : "=r"(a) : "l"(p));
    return a;
}
__device__ __forceinline__ void cp_async16(uint32_t dst, const void* src) {
    asm volatile("cp.async.cg.shared.global [%0], [%1], 16;" :: "r"(dst), "l"(src));
}
#define CP_COMMIT() asm volatile("cp.async.commit_group;" ::: "memory")
#define CP_WAIT0()  asm volatile("cp.async.wait_group 0;" ::: "memory")
#define CP_WAIT1()  asm volatile("cp.async.wait_group 1;" ::: "memory")

__device__ __forceinline__ void ldsm_x4(uint32_t a, uint32_t* r) {
    asm volatile("ldmatrix.sync.aligned.m8n8.x4.shared.b16 {%0,%1,%2,%3}, [%4];"
                 : "=r"(r[0]), "=r"(r[1]), "=r"(r[2]), "=r"(r[3]) : "r"(a));
}
__device__ __forceinline__ void ldsm_x2(uint32_t a, uint32_t* r) {
    asm volatile("ldmatrix.sync.aligned.m8n8.x2.shared.b16 {%0,%1}, [%2];"
                 : "=r"(r[0]), "=r"(r[1]) : "r"(a));
}
__device__ __forceinline__ void ldsm_x4t(uint32_t a, uint32_t* r) {
    asm volatile("ldmatrix.sync.aligned.m8n8.x4.trans.shared.b16 {%0,%1,%2,%3}, [%4];"
                 : "=r"(r[0]), "=r"(r[1]), "=r"(r[2]), "=r"(r[3]) : "r"(a));
}
__device__ __forceinline__ void mma16816(float* c, const uint32_t* a, const uint32_t* b) {
    asm volatile("mma.sync.aligned.m16n8k16.row.col.f32.bf16.bf16.f32 "
                 "{%0,%1,%2,%3},{%4,%5,%6,%7},{%8,%9},{%0,%1,%2,%3};"
                 : "+f"(c[0]), "+f"(c[1]), "+f"(c[2]), "+f"(c[3])
                 : "r"(a[0]), "r"(a[1]), "r"(a[2]), "r"(a[3]), "r"(b[0]), "r"(b[1]));
}
__device__ __forceinline__ uint32_t packbf(float lo, float hi) {
    uint32_t r; asm("cvt.rn.bf16x2.f32 %0, %1, %2;" : "=r"(r) : "f"(hi), "f"(lo)); return r;
}

__device__ __forceinline__ float fexp(float x) {
    x = fmaxf(x, -80.f);
    float y = x * 1.442695041f;
    float n = rintf(y);
    float f = y - n;
    float p =            1.8775767e-3f;
    p = fmaf(p, f, 8.9893397e-3f);
    p = fmaf(p, f, 5.5826318e-2f);
    p = fmaf(p, f, 2.4015361e-1f);
    p = fmaf(p, f, 6.9315308e-1f);
    p = fmaf(p, f, 9.9999994e-1f);
    return __int_as_float(__float_as_int(p) + ((int)n << 23));
}
__device__ __forceinline__ float ftanh(float x) {
    float ax = fabsf(x);
    float e = fexp(-2.f * ax);
    float d = 1.f + e;
    float r = fmaf(-0.5f, d, 1.4571f);
    r = r * fmaf(-d, r, 2.f);
    r = r * fmaf(-d, r, 2.f);
    r = r * fmaf(-d, r, 2.f);
    float t = (1.f - e) * r;
    return (x >= 0.f) ? t : -t;
}
__device__ __forceinline__ void split3(__nv_bfloat16* p, float v) {
    __nv_bfloat16 hi = __float2bfloat16(v);
    __nv_bfloat16 lo = __float2bfloat16(v - __bfloat162float(hi));
    p[0] = hi; p[Dm] = hi; p[2*Dm] = lo;
}

// -------- prep: weight packs + rope tables + layernorm(split) --------
#define NB_WQKV 28224
#define NB_WO   9408
#define NB_ROPE 128
__global__ void prep_kernel(const float* __restrict__ Wq, const float* __restrict__ Wk,
                            const float* __restrict__ Wv, const float* __restrict__ Wo,
                            const float* __restrict__ x, const float* __restrict__ lng,
                            const float* __restrict__ lnb,
                            __nv_bfloat16* __restrict__ wqkv, __nv_bfloat16* __restrict__ wocat,
                            float* __restrict__ cc, float* __restrict__ ss,
                            __nv_bfloat16* __restrict__ y)
{
    int bid = blockIdx.x, tid = threadIdx.x;
    if (bid < NB_WQKV) {
        size_t idx = (size_t)bid * 256 + tid;
        int k = (int)(idx % KCAT), n = (int)(idx / KCAT);
        const float* W = (n < Dm) ? Wq : ((n < 2*Dm) ? Wk : Wv);
        int c = n % Dm, kr = k % Dm, blk = k / Dm;
        float w = W[(size_t)kr * Dm + c];
        __nv_bfloat16 hi = __float2bfloat16(w);
        wqkv[idx] = (blk == 1) ? __float2bfloat16(w - __bfloat162float(hi)) : hi;
    } else if (bid < NB_WQKV + NB_WO) {
        size_t idx = (size_t)(bid - NB_WQKV) * 256 + tid;
        int k = (int)(idx % KCAT), n = (int)(idx / KCAT);
        int kr = k % Dm, blk = k / Dm;
        float w = Wo[(size_t)kr * Dm + n];
        __nv_bfloat16 hi = __float2bfloat16(w);
        wocat[idx] = (blk == 1) ? __float2bfloat16(w - __bfloat162float(hi)) : hi;
    } else if (bid < NB_WQKV + NB_WO + NB_ROPE) {
        int i = (bid - NB_WQKV - NB_WO) * 256 + tid;
        int n = i >> 5, d = i & 31;
        float freq = (float)n * powf(10000.f, -(float)(2*d) / 64.f);
        cc[i] = cosf(freq);
        ss[i] = sinf(freq);
    } else {
        int row = bid - (NB_WQKV + NB_WO + NB_ROPE);
        const float* xr = x + (size_t)row * Dm;
        float s = 0.f, s2 = 0.f;
        for (int i = tid; i < Dm; i += 256) { float v = xr[i]; s += v; s2 += v*v; }
        #pragma unroll
        for (int o = 16; o; o >>= 1) { s += __shfl_xor_sync(~0u, s, o); s2 += __shfl_xor_sync(~0u, s2, o); }
        __shared__ float ws[8], ws2[8];
        int w = tid >> 5;
        if ((tid & 31) == 0) { ws[w] = s; ws2[w] = s2; }
        __syncthreads();
        if (tid < 32) {
            s  = (tid < 8) ? ws[tid]  : 0.f;
            s2 = (tid < 8) ? ws2[tid] : 0.f;
            #pragma unroll
            for (int o = 4; o; o >>= 1) { s += __shfl_xor_sync(~0u, s, o); s2 += __shfl_xor_sync(~0u, s2, o); }
            if (tid == 0) { ws[0] = s; ws2[0] = s2; }
        }
        __syncthreads();
        float mu  = ws[0] * (1.f/Dm);
        float var = ws2[0] * (1.f/Dm) - mu*mu;
        float inv = rsqrtf(var + 1e-5f);
        __nv_bfloat16* yr = y + (size_t)row * KCAT;
        for (int i = tid; i < Dm; i += 256) {
            float v = (xr[i] - mu) * inv * lng[i] + lnb[i];
            split3(yr + i, v);
        }
    }
}

// -------- bias precompute --------
__global__ void bias_kernel(const float* __restrict__ bear, const float* __restrict__ wd,
                            const float* __restrict__ adj, const float* __restrict__ ww,
                            const float* __restrict__ wbv, float* __restrict__ bias)
{
    int t = blockIdx.x;
    int b = blockIdx.y;
    int q0 = (t >> 5) * 32, k0 = (t & 31) * 32;
    __shared__ float tile[32][33];
    __shared__ float w0s[Hh], w1s[Hh], wbs[Hh];
    int tid = threadIdx.x;
    int j = tid & 31, i = tid >> 5;
    if (tid < Hh) { w0s[tid] = ww[tid]; w1s[tid] = ww[Hh + tid]; wbs[tid] = wbv[tid]; }
    #pragma unroll
    for (int p = 0; p < 4; p++)
        tile[i + p*8][j] = bear[(size_t)(k0 + i + p*8) * Nn + q0 + j];
    __syncthreads();
    #pragma unroll
    for (int p = 0; p < 4; p++) {
        int qi = i + p*8;
        int q = q0 + qi, k = k0 + j;
        float rb = fmodf(tile[j][qi] + 180.f, 360.f);
        float av = cosf((wd[b*Nn + q] - rb) * 0.017453292519943295f);
        float a  = adj[(size_t)q * Nn + k];
        bool on = (a > 0.f);
        size_t base = ((size_t)q << 10) + k;
        #pragma unroll
        for (int h = 0; h < Hh; h++) {
            float bv = on ? ftanh(fmaf(av, w0s[h], fmaf(a, w1s[h], wbs[h]))) : -1e30f;
            bias[(((size_t)(b*Hh + h)) << 20) + base] = bv;
        }
    }
}

// -------- gemm stage loader --------
__device__ __forceinline__ void load_stage(uint32_t abase, uint32_t bbase,
                                           const __nv_bfloat16* __restrict__ A,
                                           const __nv_bfloat16* __restrict__ Bw,
                                           int m0, int n0, int k0)
{
    int tid = threadIdx.x;
    #pragma unroll
    for (int p = 0; p < 2; p++) {
        int e = p * 256 + tid;
        int r = e >> 2, seg = e & 3;
        cp_async16(abase + r * 80 + seg * 16, A + (size_t)(m0 + r) * KCAT + k0 + seg * 8);
    }
    #pragma unroll
    for (int p = 0; p < 2; p++) {
        int e = p * 256 + tid;
        int r = e >> 2, seg = e & 3;
        cp_async16(bbase + r * 80 + seg * 16, Bw + (size_t)(n0 + r) * KCAT + k0 + seg * 8);
    }
}

// -------- mma GEMM --------
template<int MODE>
__global__ void __launch_bounds__(256, 2)
gemm_mma(const __nv_bfloat16* __restrict__ A, const __nv_bfloat16* __restrict__ Bw,
         const float* __restrict__ cosp, const float* __restrict__ sinp,
         const float* __restrict__ res, void* outQ, void* outK, void* outV)
{
    extern __shared__ char dsm[];
    uint32_t sb = smem_u32(dsm);
    float* sep = (float*)dsm;

    int tid = threadIdx.x, wid = tid >> 5, lane = tid & 31;
    int wm = wid >> 2, wn = wid & 3;
    int m0 = blockIdx.y * 128, n0 = blockIdx.x * 128;

    float acc[4][4][4];
    #pragma unroll
    for (int i = 0; i < 4; i++)
        #pragma unroll
        for (int j = 0; j < 4; j++)
            #pragma unroll
            for (int r = 0; r < 4; r++) acc[i][j][r] = 0.f;

    int gq = lane >> 3, lr = lane & 7;
    uint32_t a_off = (uint32_t)((wm*64 + lr + (gq & 1)*8) * 80 + (gq >> 1)*16);
    uint32_t b_off = (uint32_t)((wn*32 + lr) * 80 + ((lane & 8) ? 16 : 0));

    load_stage(sb + 0*STG, sb + 0*STG + 10240, A, Bw, m0, n0, 0);
    CP_COMMIT();
    load_stage(sb + 1*STG, sb + 1*STG + 10240, A, Bw, m0, n0, 32);
    CP_COMMIT();

    const int NT = KCAT / 32;
    int slot = 0;
    for (int i = 0; i < NT; i++) {
        if (i + 1 < NT) CP_WAIT1(); else CP_WAIT0();
        __syncthreads();
        uint32_t ab = sb + slot * STG, bb = ab + 10240;
        #pragma unroll
        for (int ks = 0; ks < 2; ks++) {
            uint32_t afr[4][4], bfr[4][2];
            #pragma unroll
            for (int mt = 0; mt < 4; mt++) ldsm_x4(ab + a_off + mt*(16*80) + ks*32, afr[mt]);
            #pragma unroll
            for (int nt = 0; nt < 4; nt++) ldsm_x2(bb + b_off + nt*(8*80) + ks*32, bfr[nt]);
            #pragma unroll
            for (int mt = 0; mt < 4; mt++)
                #pragma unroll
                for (int nt = 0; nt < 4; nt++)
                    mma16816(acc[mt][nt], afr[mt], bfr[nt]);
        }
        if (i + 2 < NT) {
            int ns = slot + 2; if (ns >= 3) ns -= 3;
            uint32_t nb = sb + ns * STG;
            load_stage(nb, nb + 10240, A, Bw, m0, n0, (i + 2) * 32);
            CP_COMMIT();
        }
        slot++; if (slot == 3) slot = 0;
    }
    __syncthreads();

    #pragma unroll
    for (int half = 0; half < 2; half++) {
        if (wm == half) {
            #pragma unroll
            for (int mt = 0; mt < 4; mt++)
                #pragma unroll
                for (int nt = 0; nt < 4; nt++)
                    #pragma unroll
                    for (int ri = 0; ri < 4; ri++) {
                        int r = mt*16 + (lane >> 2) + ((ri >> 1) * 8);
                        int n = wn*32 + nt*8 + ((lane & 3) * 2) + (ri & 1);
                        sep[r * EPITCH + n] = acc[mt][nt][ri];
                    }
        }
        __syncthreads();

        if (MODE == 0) {
            int tile = blockIdx.x;
            int region = tile / 7;
            int cbase = (tile % 7) * 128;
            __nv_bfloat16* base = (region == 0) ? (__nv_bfloat16*)outQ
                                : (region == 1) ? (__nv_bfloat16*)outK
                                                : (__nv_bfloat16*)outV;
            for (int idx = tid; idx < 64*128; idx += 256) {
                int r = idx >> 7, c = idx & 127;
                int m = m0 + half*64 + r;
                int bqi = m >> 10, n = m & 1023;
                int ccx = cbase + c;
                int head = ccx >> 6, d = ccx & 63;
                float val;
                if (region < 2) {
                    if (d < 32) {
                        float x1 = sep[r*EPITCH + c], x2 = sep[r*EPITCH + c + 32];
                        val = x1 * cosp[n*32 + d] - x2 * sinp[n*32 + d];
                    } else {
                        float x2 = sep[r*EPITCH + c], x1 = sep[r*EPITCH + c - 32];
                        int dd = d - 32;
                        val = x2 * cosp[n*32 + dd] + x1 * sinp[n*32 + dd];
                    }
                } else {
                    val = sep[r*EPITCH + c];
                }
                __nv_bfloat16 hv = __float2bfloat16(val);
                __nv_bfloat16 lv = __float2bfloat16(val - __bfloat162float(hv));
                size_t row = ((size_t)bqi * Hh + head) * Nn + n;
                base[row*128 + d]      = hv;
                base[row*128 + 64 + d] = lv;
            }
        } else {
            float* outp = (float*)outQ;
            for (int idx = tid; idx < 64*128; idx += 256) {
                int r = idx >> 7, c = idx & 127;
                int m = m0 + half*64 + r;
                size_t o = (size_t)m * Dm + n0 + c;
                outp[o] = sep[r*EPITCH + c] + res[o];
            }
        }
        __syncthreads();
    }
}

// -------- attn chunk loader: 64 rows x 256B, pitch 272, 256 threads --------
__device__ __forceinline__ void ld_chunk64(uint32_t dst, const __nv_bfloat16* __restrict__ src,
                                           int tok0)
{
    #pragma unroll
    for (int p = 0; p < 4; p++) {
        int e = p * 256 + threadIdx.x;
        int r = e >> 4, s = e & 15;
        cp_async16(dst + r * 272 + s * 16, src + (size_t)(tok0 + r) * 128 + s * 8);
    }
}
__device__ __forceinline__ void pfrag_pair(const float* sc, int r, int c,
                                           uint32_t& phi, uint32_t& plo)
{
    float2 p = *(const float2*)(sc + r * SCP + c);
    float h0 = __bfloat162float(__float2bfloat16(p.x));
    float h1 = __bfloat162float(__float2bfloat16(p.y));
    phi = packbf(p.x, p.y);
    plo = packbf(p.x - h0, p.y - h1);
}

// -------- mma attention: block (b,h,16q), 256 threads, occ 2 --------
__global__ void __launch_bounds__(256, 2)
attn_mma(const __nv_bfloat16* __restrict__ Qc, const __nv_bfloat16* __restrict__ Kc,
         const __nv_bfloat16* __restrict__ Vc, const float* __restrict__ bias,
         __nv_bfloat16* __restrict__ out)
{
    extern __shared__ char dsm[];
    float* sc = (float*)dsm;                       // [16][SCP]
    const int SCB = 16 * SCP * 4;                  // 66048
    uint32_t sb = smem_u32(dsm);
    uint32_t qs = sb + SCB;                        // Q tile 16 x 272 = 4352
    uint32_t bu0 = qs + 16*272;                    // 64 x 272 = 17408
    uint32_t bu1 = bu0 + 64*272;
    float* part = (float*)(dsm + SCB + 16*272);    // overlays bu0 after PV (16 KB)

    int tid = threadIdx.x, wid = tid >> 5, lane = tid & 31;
    int h = blockIdx.y, b = blockIdx.z;
    int q0 = blockIdx.x * 16;
    size_t bh = ((size_t)b * Hh + h) * Nn;
    const __nv_bfloat16* Kbh = Kc + bh * 128;
    const __nv_bfloat16* Vbh = Vc + bh * 128;
    const float* biasbh = bias + (((size_t)(b*Hh + h)) << 20);

    {   // Q tile: 256 transfers, one per thread
        int r = tid >> 4, s = tid & 15;
        cp_async16(qs + r*272 + s*16, Qc + (bh + q0 + r) * 128 + s * 8);
    }
    CP_COMMIT();
    ld_chunk64(bu0, Kbh, 0);  CP_COMMIT();
    ld_chunk64(bu1, Kbh, 64); CP_COMMIT();

    int r_ = lane >> 2, cl = 2*(lane & 3);

    // ---- scores: S = (qhi.khi + qhi.klo + qlo.khi)*0.125 + bias ----
    {
        uint32_t afr[8][4];
        int gq = lane >> 3, lr = lane & 7;
        uint32_t a_off = qs + (uint32_t)((lr + (gq & 1)*8) * 272 + (gq >> 1)*16);

        // bias double-buffer in registers
        const float* bb0 = biasbh + (((size_t)(q0 + r_))     << 10) + wid*8 + cl;
        const float* bb1 = biasbh + (((size_t)(q0 + r_ + 8)) << 10) + wid*8 + cl;
        float2 nb0 = *(const float2*)bb0;
        float2 nb1 = *(const float2*)bb1;

        for (int c = 0; c < NCH; c++) {
            float2 u0 = nb0, u1 = nb1;
            if (c + 1 < NCH) {
                nb0 = *(const float2*)(bb0 + (c + 1) * 64);
                nb1 = *(const float2*)(bb1 + (c + 1) * 64);
            }
            if (c < NCH-1) CP_WAIT1(); else CP_WAIT0();
            __syncthreads();
            if (c == 0) {
                #pragma unroll
                for (int kt = 0; kt < 8; kt++) ldsm_x4(a_off + kt*32, afr[kt]);
            }
            uint32_t kb = (c & 1) ? bu1 : bu0;
            uint32_t bbw = kb + (uint32_t)((wid*8 + (lane & 7)) * 272 + ((lane >> 3) & 1) * 16);
            uint32_t bf[8][2];
            #pragma unroll
            for (int j = 0; j < 8; j++) ldsm_x2(bbw + j*32, bf[j]);
            float dd[4] = {0.f, 0.f, 0.f, 0.f};
            #pragma unroll
            for (int t = 0; t < 4; t++) mma16816(dd, afr[t],   bf[t]);
            #pragma unroll
            for (int t = 0; t < 4; t++) mma16816(dd, afr[t],   bf[4+t]);
            #pragma unroll
            for (int t = 0; t < 4; t++) mma16816(dd, afr[4+t], bf[t]);
            int col = c*64 + wid*8 + cl;
            *(float2*)(sc + r_*SCP + col) =
                make_float2(fmaf(dd[0], 0.125f, u0.x), fmaf(dd[1], 0.125f, u0.y));
            *(float2*)(sc + (r_+8)*SCP + col) =
                make_float2(fmaf(dd[2], 0.125f, u1.x), fmaf(dd[3], 0.125f, u1.y));
            __syncthreads();
            if (c + 2 < NCH) { ld_chunk64(kb, Kbh, (c + 2) * 64); CP_COMMIT(); }
        }
    }

    // prefetch V chunks 0,1 (K buffers free)
    ld_chunk64(bu0, Vbh, 0);  CP_COMMIT();
    ld_chunk64(bu1, Vbh, 64); CP_COMMIT();

    // ---- softmax: 8 warps x 2 rows, normalize inline ----
    #pragma unroll
    for (int rr = 0; rr < 2; rr++) {
        float* row = sc + (wid + rr*8) * SCP;
        float mx = -1e30f;
        for (int k = lane; k < 1024; k += 32) mx = fmaxf(mx, row[k]);
        #pragma unroll
        for (int o = 16; o; o >>= 1) mx = fmaxf(mx, __shfl_xor_sync(~0u, mx, o));
        float sm = 0.f;
        for (int k = lane; k < 1024; k += 32) {
            float e = fexp(row[k] - mx);
            row[k] = e;
            sm += e;
        }
        #pragma unroll
        for (int o = 16; o; o >>= 1) sm += __shfl_xor_sync(~0u, sm, o);
        float inv = 1.f / sm;
        for (int k = lane; k < 1024; k += 32) row[k] *= inv;
    }
    __syncthreads();

    // ---- PV: warps (kw = wid&3 over 16-token windows, nw = wid>>2 over 32-d halves) ----
    int kw = wid & 3, nw = wid >> 2;
    float acc[4][4];
    #pragma unroll
    for (int nt = 0; nt < 4; nt++)
        #pragma unroll
        for (int r = 0; r < 4; r++) acc[nt][r] = 0.f;

    for (int c = 0; c < NCH; c++) {
        if (c < NCH-1) CP_WAIT1(); else CP_WAIT0();
        __syncthreads();
        uint32_t vb = (c & 1) ? bu1 : bu0;
        int tokb = c*64 + kw*16;

        uint32_t phi[4], plo[4];
        {
            int cb = tokb + cl;
            pfrag_pair(sc, r_,     cb,     phi[0], plo[0]);
            pfrag_pair(sc, r_ + 8, cb,     phi[1], plo[1]);
            pfrag_pair(sc, r_,     cb + 8, phi[2], plo[2]);
            pfrag_pair(sc, r_ + 8, cb + 8, phi[3], plo[3]);
        }
        uint32_t vaddr = vb + (uint32_t)((kw*16 + ((lane >> 3) & 1)*8 + (lane & 7)) * 272
                                         + ((lane >> 4) & 1) * 16 + nw*64);
        uint32_t vfh[4][2], vfl[4][2];
        #pragma unroll
        for (int p = 0; p < 2; p++) {
            uint32_t r4[4];
            ldsm_x4t(vaddr + p*32, r4);
            vfh[2*p][0] = r4[0]; vfh[2*p][1] = r4[1];
            vfh[2*p+1][0] = r4[2]; vfh[2*p+1][1] = r4[3];
            ldsm_x4t(vaddr + 128 + p*32, r4);
            vfl[2*p][0] = r4[0]; vfl[2*p][1] = r4[1];
            vfl[2*p+1][0] = r4[2]; vfl[2*p+1][1] = r4[3];
        }
        #pragma unroll
        for (int nt = 0; nt < 4; nt++) {
            mma16816(acc[nt], phi, vfh[nt]);
            mma16816(acc[nt], phi, vfl[nt]);
            mma16816(acc[nt], plo, vfh[nt]);
        }
        __syncthreads();
        if (c + 2 < NCH) { ld_chunk64(vb, Vbh, (c + 2) * 64); CP_COMMIT(); }
    }

    // ---- cross-warp reduce: part[kw][16][64] ----
    #pragma unroll
    for (int nt = 0; nt < 4; nt++) {
        int d = nw*32 + nt*8 + cl;
        *(float2*)(part + kw*1024 + r_*64 + d)     = make_float2(acc[nt][0], acc[nt][1]);
        *(float2*)(part + kw*1024 + (r_+8)*64 + d) = make_float2(acc[nt][2], acc[nt][3]);
    }
    __syncthreads();
    for (int o = tid; o < 1024; o += 256) {
        float s = part[o] + part[1024 + o] + part[2048 + o] + part[3072 + o];
        int qi = o >> 6, d = o & 63;
        int col = h * 64 + d;
        split3(out + (size_t)(b * Nn + q0 + qi) * KCAT + col, s);
    }
}

// -------------------- launch --------------------
extern "C" void kernel_launch(void* const* d_in, const int* in_sizes, int n_in,
                              void* d_out, int out_size)
{
    const float* node = (const float*)d_in[0];
    const float* adj  = (const float*)d_in[1];
    const float* wd   = (const float*)d_in[2];
    const float* bear = (const float*)d_in[3];
    const float* Wq   = (const float*)d_in[4];
    const float* Wk   = (const float*)d_in[5];
    const float* Wv   = (const float*)d_in[6];
    const float* Wo   = (const float*)d_in[7];
    const float* lng  = (const float*)d_in[8];
    const float* lnb  = (const float*)d_in[9];
    const float* ww   = (const float*)d_in[10];
    const float* wbv  = (const float*)d_in[11];
    float* out = (float*)d_out;

    __nv_bfloat16 *xcat, *wqkv, *wocat, *aocat, *Qc, *Kc, *Vc;
    float *biasp, *cosp, *sinp;
    cudaGetSymbolAddress((void**)&xcat,  g_xcat);
    cudaGetSymbolAddress((void**)&wqkv,  g_wqkv);
    cudaGetSymbolAddress((void**)&wocat, g_wocat);
    cudaGetSymbolAddress((void**)&aocat, g_aocat);
    cudaGetSymbolAddress((void**)&Qc,    g_Qc);
    cudaGetSymbolAddress((void**)&Kc,    g_Kc);
    cudaGetSymbolAddress((void**)&Vc,    g_Vc);
    cudaGetSymbolAddress((void**)&biasp, g_bias);
    cudaGetSymbolAddress((void**)&cosp,  g_cos);
    cudaGetSymbolAddress((void**)&sinp,  g_sin);

    const int SMEM_GEMM = 3 * STG;
    const int SMEM_ATTN = 16*SCP*4 + 16*272 + 2*64*272;   // 105216 -> occ 2
    cudaFuncSetAttribute(gemm_mma<0>, cudaFuncAttributeMaxDynamicSharedMemorySize, SMEM_GEMM);
    cudaFuncSetAttribute(gemm_mma<1>, cudaFuncAttributeMaxDynamicSharedMemorySize, SMEM_GEMM);
    cudaFuncSetAttribute(attn_mma,    cudaFuncAttributeMaxDynamicSharedMemorySize, SMEM_ATTN);

    prep_kernel<<<NB_WQKV + NB_WO + NB_ROPE + BN, 256>>>(Wq, Wk, Wv, Wo, node, lng, lnb,
                                                         wqkv, wocat, cosp, sinp, xcat);
    bias_kernel<<<dim3(1024, Bq), 256>>>(bear, wd, adj, ww, wbv, biasp);
    gemm_mma<0><<<dim3(KCAT/128, BN/128), 256, SMEM_GEMM>>>(xcat, wqkv, cosp, sinp,
                                                            nullptr, Qc, Kc, Vc);
    attn_mma<<<dim3(Nn/16, Hh, Bq), 256, SMEM_ATTN>>>(Qc, Kc, Vc, biasp, aocat);
    gemm_mma<1><<<dim3(Dm/128, BN/128), 256, SMEM_GEMM>>>(aocat, wocat, cosp, sinp,
                                                          node, out, nullptr, nullptr);
}

// round 10
// speedup vs baseline: 2.1980x; 1.0698x over previous
#include <cuda_runtime.h>
#include <cuda_bf16.h>
#include <math.h>
#include <stdint.h>

#define Bq   8
#define Nn   1024
#define Dm   896
#define Hh   14
#define Dh   64
#define BN   (Bq*Nn)
#define KCAT 2688
#define EPITCH 132
#define STG  20480

__device__ __align__(128) __nv_bfloat16 g_xcat[(size_t)BN*KCAT];
__device__ __align__(128) __nv_bfloat16 g_wqkv[(size_t)KCAT*KCAT];
__device__ __align__(128) __nv_bfloat16 g_wocat[(size_t)Dm*KCAT];
__device__ __align__(128) __nv_bfloat16 g_aocat[(size_t)BN*KCAT];
__device__ __align__(128) __nv_bfloat16 g_Qc[(size_t)Bq*Hh*Nn*128];
__device__ __align__(128) __nv_bfloat16 g_Kc[(size_t)Bq*Hh*Nn*128];
__device__ __align__(128) __nv_bfloat16 g_Vc[(size_t)Bq*Hh*Nn*128];
__device__ float g_bias[(size_t)Bq*Hh*Nn*Nn];
__device__ float g_cos[Nn*32];
__device__ float g_sin[Nn*32];

__device__ __forceinline__ uint32_t smem_u32(const void* p) {
    uint32_t a;
    asm("{ .reg .u64 t; cvta.to.shared.u64 t, %1; cvt.u32.u64 %0, t; }" : "=r"(a) : "l"(p));
    return a;
}
__device__ __forceinline__ void cp_async16(uint32_t dst, const void* src) {
    asm volatile("cp.async.cg.shared.global [%0], [%1], 16;" :: "r"(dst), "l"(src));
}
#define CP_COMMIT() asm volatile("cp.async.commit_group;" ::: "memory")
#define CP_WAIT0()  asm volatile("cp.async.wait_group 0;" ::: "memory")
#define CP_WAIT1()  asm volatile("cp.async.wait_group 1;" ::: "memory")

__device__ __forceinline__ void ldsm_x4(uint32_t a, uint32_t* r) {
    asm volatile("ldmatrix.sync.aligned.m8n8.x4.shared.b16 {%0,%1,%2,%3}, [%4];"
                 : "=r"(r[0]), "=r"(r[1]), "=r"(r[2]), "=r"(r[3]) : "r"(a));
}
__device__ __forceinline__ void ldsm_x2(uint32_t a, uint32_t* r) {
    asm volatile("ldmatrix.sync.aligned.m8n8.x2.shared.b16 {%0,%1}, [%2];"
                 : "=r"(r[0]), "=r"(r[1]) : "r"(a));
}
__device__ __forceinline__ void ldsm_x4t(uint32_t a, uint32_t* r) {
    asm volatile("ldmatrix.sync.aligned.m8n8.x4.trans.shared.b16 {%0,%1,%2,%3}, [%4];"
                 : "=r"(r[0]), "=r"(r[1]), "=r"(r[2]), "=r"(r[3]) : "r"(a));
}
__device__ __forceinline__ void mma16816(float* c, const uint32_t* a, const uint32_t* b) {
    asm volatile("mma.sync.aligned.m16n8k16.row.col.f32.bf16.bf16.f32 "
                 "{%0,%1,%2,%3},{%4,%5,%6,%7},{%8,%9},{%0,%1,%2,%3};"
                 : "+f"(c[0]), "+f"(c[1]), "+f"(c[2]), "+f"(c[3])
                 : "r"(a[0]), "r"(a[1]), "r"(a[2]), "r"(a[3]), "r"(b[0]), "r"(b[1]));
}
__device__ __forceinline__ uint32_t packbf(float lo, float hi) {
    uint32_t r; asm("cvt.rn.bf16x2.f32 %0, %1, %2;" : "=r"(r) : "f"(hi), "f"(lo)); return r;
}

__device__ __forceinline__ float fexp(float x) {
    x = fmaxf(x, -80.f);
    float y = x * 1.442695041f;
    float n = rintf(y);
    float f = y - n;
    float p =            1.8775767e-3f;
    p = fmaf(p, f, 8.9893397e-3f);
    p = fmaf(p, f, 5.5826318e-2f);
    p = fmaf(p, f, 2.4015361e-1f);
    p = fmaf(p, f, 6.9315308e-1f);
    p = fmaf(p, f, 9.9999994e-1f);
    return __int_as_float(__float_as_int(p) + ((int)n << 23));
}
__device__ __forceinline__ float ftanh(float x) {
    float ax = fabsf(x);
    float e = fexp(-2.f * ax);
    float d = 1.f + e;
    float r = fmaf(-0.5f, d, 1.4571f);
    r = r * fmaf(-d, r, 2.f);
    r = r * fmaf(-d, r, 2.f);
    r = r * fmaf(-d, r, 2.f);
    float t = (1.f - e) * r;
    return (x >= 0.f) ? t : -t;
}
__device__ __forceinline__ void split3(__nv_bfloat16* p, float v) {
    __nv_bfloat16 hi = __float2bfloat16(v);
    __nv_bfloat16 lo = __float2bfloat16(v - __bfloat162float(hi));
    p[0] = hi; p[Dm] = hi; p[2*Dm] = lo;
}
// p,q -> bf16 hi frag + residual lo frag
__device__ __forceinline__ void psplit(float x, float y, uint32_t& hi, uint32_t& lo) {
    float hx = __bfloat162float(__float2bfloat16(x));
    float hy = __bfloat162float(__float2bfloat16(y));
    hi = packbf(x, y);
    lo = packbf(x - hx, y - hy);
}

// -------- prep: weight packs + rope tables + layernorm(split) --------
#define NB_WQKV 28224
#define NB_WO   9408
#define NB_ROPE 128
__global__ void prep_kernel(const float* __restrict__ Wq, const float* __restrict__ Wk,
                            const float* __restrict__ Wv, const float* __restrict__ Wo,
                            const float* __restrict__ x, const float* __restrict__ lng,
                            const float* __restrict__ lnb,
                            __nv_bfloat16* __restrict__ wqkv, __nv_bfloat16* __restrict__ wocat,
                            float* __restrict__ cc, float* __restrict__ ss,
                            __nv_bfloat16* __restrict__ y)
{
    int bid = blockIdx.x, tid = threadIdx.x;
    if (bid < NB_WQKV) {
        size_t idx = (size_t)bid * 256 + tid;
        int k = (int)(idx % KCAT), n = (int)(idx / KCAT);
        const float* W = (n < Dm) ? Wq : ((n < 2*Dm) ? Wk : Wv);
        int c = n % Dm, kr = k % Dm, blk = k / Dm;
        float w = W[(size_t)kr * Dm + c];
        __nv_bfloat16 hi = __float2bfloat16(w);
        wqkv[idx] = (blk == 1) ? __float2bfloat16(w - __bfloat162float(hi)) : hi;
    } else if (bid < NB_WQKV + NB_WO) {
        size_t idx = (size_t)(bid - NB_WQKV) * 256 + tid;
        int k = (int)(idx % KCAT), n = (int)(idx / KCAT);
        int kr = k % Dm, blk = k / Dm;
        float w = Wo[(size_t)kr * Dm + n];
        __nv_bfloat16 hi = __float2bfloat16(w);
        wocat[idx] = (blk == 1) ? __float2bfloat16(w - __bfloat162float(hi)) : hi;
    } else if (bid < NB_WQKV + NB_WO + NB_ROPE) {
        int i = (bid - NB_WQKV - NB_WO) * 256 + tid;
        int n = i >> 5, d = i & 31;
        float freq = (float)n * powf(10000.f, -(float)(2*d) / 64.f);
        cc[i] = cosf(freq);
        ss[i] = sinf(freq);
    } else {
        int row = bid - (NB_WQKV + NB_WO + NB_ROPE);
        const float* xr = x + (size_t)row * Dm;
        float s = 0.f, s2 = 0.f;
        for (int i = tid; i < Dm; i += 256) { float v = xr[i]; s += v; s2 += v*v; }
        #pragma unroll
        for (int o = 16; o; o >>= 1) { s += __shfl_xor_sync(~0u, s, o); s2 += __shfl_xor_sync(~0u, s2, o); }
        __shared__ float ws[8], ws2[8];
        int w = tid >> 5;
        if ((tid & 31) == 0) { ws[w] = s; ws2[w] = s2; }
        __syncthreads();
        if (tid < 32) {
            s  = (tid < 8) ? ws[tid]  : 0.f;
            s2 = (tid < 8) ? ws2[tid] : 0.f;
            #pragma unroll
            for (int o = 4; o; o >>= 1) { s += __shfl_xor_sync(~0u, s, o); s2 += __shfl_xor_sync(~0u, s2, o); }
            if (tid == 0) { ws[0] = s; ws2[0] = s2; }
        }
        __syncthreads();
        float mu  = ws[0] * (1.f/Dm);
        float var = ws2[0] * (1.f/Dm) - mu*mu;
        float inv = rsqrtf(var + 1e-5f);
        __nv_bfloat16* yr = y + (size_t)row * KCAT;
        for (int i = tid; i < Dm; i += 256) {
            float v = (xr[i] - mu) * inv * lng[i] + lnb[i];
            split3(yr + i, v);
        }
    }
}

// -------- bias precompute --------
__global__ void bias_kernel(const float* __restrict__ bear, const float* __restrict__ wd,
                            const float* __restrict__ adj, const float* __restrict__ ww,
                            const float* __restrict__ wbv, float* __restrict__ bias)
{
    int t = blockIdx.x;
    int b = blockIdx.y;
    int q0 = (t >> 5) * 32, k0 = (t & 31) * 32;
    __shared__ float tile[32][33];
    __shared__ float w0s[Hh], w1s[Hh], wbs[Hh];
    int tid = threadIdx.x;
    int j = tid & 31, i = tid >> 5;
    if (tid < Hh) { w0s[tid] = ww[tid]; w1s[tid] = ww[Hh + tid]; wbs[tid] = wbv[tid]; }
    #pragma unroll
    for (int p = 0; p < 4; p++)
        tile[i + p*8][j] = bear[(size_t)(k0 + i + p*8) * Nn + q0 + j];
    __syncthreads();
    #pragma unroll
    for (int p = 0; p < 4; p++) {
        int qi = i + p*8;
        int q = q0 + qi, k = k0 + j;
        float rb = fmodf(tile[j][qi] + 180.f, 360.f);
        float av = cosf((wd[b*Nn + q] - rb) * 0.017453292519943295f);
        float a  = adj[(size_t)q * Nn + k];
        bool on = (a > 0.f);
        size_t base = ((size_t)q << 10) + k;
        #pragma unroll
        for (int h = 0; h < Hh; h++) {
            float bv = on ? ftanh(fmaf(av, w0s[h], fmaf(a, w1s[h], wbs[h]))) : -1e30f;
            bias[(((size_t)(b*Hh + h)) << 20) + base] = bv;
        }
    }
}

// -------- gemm stage loader --------
__device__ __forceinline__ void load_stage(uint32_t abase, uint32_t bbase,
                                           const __nv_bfloat16* __restrict__ A,
                                           const __nv_bfloat16* __restrict__ Bw,
                                           int m0, int n0, int k0)
{
    int tid = threadIdx.x;
    #pragma unroll
    for (int p = 0; p < 2; p++) {
        int e = p * 256 + tid;
        int r = e >> 2, seg = e & 3;
        cp_async16(abase + r * 80 + seg * 16, A + (size_t)(m0 + r) * KCAT + k0 + seg * 8);
    }
    #pragma unroll
    for (int p = 0; p < 2; p++) {
        int e = p * 256 + tid;
        int r = e >> 2, seg = e & 3;
        cp_async16(bbase + r * 80 + seg * 16, Bw + (size_t)(n0 + r) * KCAT + k0 + seg * 8);
    }
}

// -------- mma GEMM --------
template<int MODE>
__global__ void __launch_bounds__(256, 2)
gemm_mma(const __nv_bfloat16* __restrict__ A, const __nv_bfloat16* __restrict__ Bw,
         const float* __restrict__ cosp, const float* __restrict__ sinp,
         const float* __restrict__ res, void* outQ, void* outK, void* outV)
{
    extern __shared__ char dsm[];
    uint32_t sb = smem_u32(dsm);
    float* sep = (float*)dsm;

    int tid = threadIdx.x, wid = tid >> 5, lane = tid & 31;
    int wm = wid >> 2, wn = wid & 3;
    int m0 = blockIdx.y * 128, n0 = blockIdx.x * 128;

    float acc[4][4][4];
    #pragma unroll
    for (int i = 0; i < 4; i++)
        #pragma unroll
        for (int j = 0; j < 4; j++)
            #pragma unroll
            for (int r = 0; r < 4; r++) acc[i][j][r] = 0.f;

    int gq = lane >> 3, lr = lane & 7;
    uint32_t a_off = (uint32_t)((wm*64 + lr + (gq & 1)*8) * 80 + (gq >> 1)*16);
    uint32_t b_off = (uint32_t)((wn*32 + lr) * 80 + ((lane & 8) ? 16 : 0));

    load_stage(sb + 0*STG, sb + 0*STG + 10240, A, Bw, m0, n0, 0);
    CP_COMMIT();
    load_stage(sb + 1*STG, sb + 1*STG + 10240, A, Bw, m0, n0, 32);
    CP_COMMIT();

    const int NT = KCAT / 32;
    int slot = 0;
    for (int i = 0; i < NT; i++) {
        if (i + 1 < NT) CP_WAIT1(); else CP_WAIT0();
        __syncthreads();
        uint32_t ab = sb + slot * STG, bb = ab + 10240;
        #pragma unroll
        for (int ks = 0; ks < 2; ks++) {
            uint32_t afr[4][4], bfr[4][2];
            #pragma unroll
            for (int mt = 0; mt < 4; mt++) ldsm_x4(ab + a_off + mt*(16*80) + ks*32, afr[mt]);
            #pragma unroll
            for (int nt = 0; nt < 4; nt++) ldsm_x2(bb + b_off + nt*(8*80) + ks*32, bfr[nt]);
            #pragma unroll
            for (int mt = 0; mt < 4; mt++)
                #pragma unroll
                for (int nt = 0; nt < 4; nt++)
                    mma16816(acc[mt][nt], afr[mt], bfr[nt]);
        }
        if (i + 2 < NT) {
            int ns = slot + 2; if (ns >= 3) ns -= 3;
            uint32_t nb = sb + ns * STG;
            load_stage(nb, nb + 10240, A, Bw, m0, n0, (i + 2) * 32);
            CP_COMMIT();
        }
        slot++; if (slot == 3) slot = 0;
    }
    __syncthreads();

    #pragma unroll
    for (int half = 0; half < 2; half++) {
        if (wm == half) {
            #pragma unroll
            for (int mt = 0; mt < 4; mt++)
                #pragma unroll
                for (int nt = 0; nt < 4; nt++)
                    #pragma unroll
                    for (int ri = 0; ri < 4; ri++) {
                        int r = mt*16 + (lane >> 2) + ((ri >> 1) * 8);
                        int n = wn*32 + nt*8 + ((lane & 3) * 2) + (ri & 1);
                        sep[r * EPITCH + n] = acc[mt][nt][ri];
                    }
        }
        __syncthreads();

        if (MODE == 0) {
            int tile = blockIdx.x;
            int region = tile / 7;
            int cbase = (tile % 7) * 128;
            __nv_bfloat16* base = (region == 0) ? (__nv_bfloat16*)outQ
                                : (region == 1) ? (__nv_bfloat16*)outK
                                                : (__nv_bfloat16*)outV;
            for (int idx = tid; idx < 64*128; idx += 256) {
                int r = idx >> 7, c = idx & 127;
                int m = m0 + half*64 + r;
                int bqi = m >> 10, n = m & 1023;
                int ccx = cbase + c;
                int head = ccx >> 6, d = ccx & 63;
                float val;
                if (region < 2) {
                    if (d < 32) {
                        float x1 = sep[r*EPITCH + c], x2 = sep[r*EPITCH + c + 32];
                        val = x1 * cosp[n*32 + d] - x2 * sinp[n*32 + d];
                    } else {
                        float x2 = sep[r*EPITCH + c], x1 = sep[r*EPITCH + c - 32];
                        int dd = d - 32;
                        val = x2 * cosp[n*32 + dd] + x1 * sinp[n*32 + dd];
                    }
                } else {
                    val = sep[r*EPITCH + c];
                }
                __nv_bfloat16 hv = __float2bfloat16(val);
                __nv_bfloat16 lv = __float2bfloat16(val - __bfloat162float(hv));
                size_t row = ((size_t)bqi * Hh + head) * Nn + n;
                base[row*128 + d]      = hv;
                base[row*128 + 64 + d] = lv;
            }
        } else {
            float* outp = (float*)outQ;
            for (int idx = tid; idx < 64*128; idx += 256) {
                int r = idx >> 7, c = idx & 127;
                int m = m0 + half*64 + r;
                size_t o = (size_t)m * Dm + n0 + c;
                outp[o] = sep[r*EPITCH + c] + res[o];
            }
        }
        __syncthreads();
    }
}

// -------- flash attn chunk loader: 128 rows x 256B, pitch 272, 256 threads --------
__device__ __forceinline__ void ld_chunk128(uint32_t dst, const __nv_bfloat16* __restrict__ src,
                                            int tok0)
{
    #pragma unroll
    for (int p = 0; p < 8; p++) {
        int e = p * 256 + threadIdx.x;
        int r = e >> 4, s = e & 15;
        cp_async16(dst + r * 272 + s * 16, src + (size_t)(tok0 + r) * 128 + s * 8);
    }
}

// -------- single-pass flash attention: block (b,h,16q), 256 threads, occ 2 --------
// smem: Q 16x272 (4352) | bufA 128x272 (34816) | bufB 128x272 | mrow[128] srow[128] Sfin[16]
__global__ void __launch_bounds__(256, 2)
attn_flash(const __nv_bfloat16* __restrict__ Qc, const __nv_bfloat16* __restrict__ Kc,
           const __nv_bfloat16* __restrict__ Vc, const float* __restrict__ bias,
           __nv_bfloat16* __restrict__ out)
{
    extern __shared__ char dsm[];
    uint32_t sb = smem_u32(dsm);
    uint32_t qs = sb;
    uint32_t bufA = sb + 4352;
    uint32_t bufB = bufA + 34816;
    float* part = (float*)(dsm + 4352);                  // overlays bufA at merge
    float* mrow = (float*)(dsm + 4352 + 2*34816);        // [8][16]
    float* srow = mrow + 128;                            // [8][16]
    float* Sfin = srow + 128;                            // [16]

    int tid = threadIdx.x, wid = tid >> 5, lane = tid & 31;
    int h = blockIdx.y, b = blockIdx.z;
    int q0 = blockIdx.x * 16;
    size_t bh = ((size_t)b * Hh + h) * Nn;
    const __nv_bfloat16* Kbh = Kc + bh * 128;
    const __nv_bfloat16* Vbh = Vc + bh * 128;
    const float* biasbh = bias + (((size_t)(b*Hh + h)) << 20);

    {   // Q tile (group 0)
        int r = tid >> 4, s = tid & 15;
        cp_async16(qs + r*272 + s*16, Qc + (bh + q0 + r) * 128 + s * 8);
    }
    CP_COMMIT();
    ld_chunk128(bufA, Kbh, 0); CP_COMMIT();   // K0
    ld_chunk128(bufB, Vbh, 0); CP_COMMIT();   // V0

    int r_ = lane >> 2, cl = 2*(lane & 3);

    // bias pointers: this warp's token window base
    const float* bb0 = biasbh + (((size_t)(q0 + r_))     << 10) + wid*16;
    const float* bb1 = biasbh + (((size_t)(q0 + r_ + 8)) << 10) + wid*16;
    float2 nb00 = *(const float2*)(bb0 + cl);
    float2 nb01 = *(const float2*)(bb0 + cl + 8);
    float2 nb10 = *(const float2*)(bb1 + cl);
    float2 nb11 = *(const float2*)(bb1 + cl + 8);

    float m0 = -1e30f, m1 = -1e30f, sum0 = 0.f, sum1 = 0.f;
    float acc[8][4];
    #pragma unroll
    for (int i = 0; i < 8; i++)
        #pragma unroll
        for (int r = 0; r < 4; r++) acc[i][r] = 0.f;
    uint32_t afr[8][4];

    for (int c = 0; c < 8; c++) {
        float2 u00 = nb00, u01 = nb01, u10 = nb10, u11 = nb11;
        if (c < 7) {
            int o = (c + 1) * 128;
            nb00 = *(const float2*)(bb0 + o + cl);
            nb01 = *(const float2*)(bb0 + o + cl + 8);
            nb10 = *(const float2*)(bb1 + o + cl);
            nb11 = *(const float2*)(bb1 + o + cl + 8);
        }
        CP_WAIT1();              // K_c done (V_c pending)
        __syncthreads();
        if (c == 0) {            // hoist Q fragments
            int gq = lane >> 3, lr = lane & 7;
            uint32_t a_off = qs + (uint32_t)((lr + (gq & 1)*8) * 272 + (gq >> 1)*16);
            #pragma unroll
            for (int kt = 0; kt < 8; kt++) ldsm_x4(a_off + kt*32, afr[kt]);
        }

        // ---- scores S (16x16) for this warp's token window ----
        float dd0[4] = {0.f,0.f,0.f,0.f}, dd1[4] = {0.f,0.f,0.f,0.f};
        #pragma unroll
        for (int nt = 0; nt < 2; nt++) {
            uint32_t base = bufA + (uint32_t)((wid*16 + nt*8 + (lane & 7)) * 272
                                              + ((lane >> 3) & 1) * 16);
            uint32_t kfh[8], kfl[8];
            #pragma unroll
            for (int j = 0; j < 4; j++) ldsm_x2(base + j*32, kfh + 2*j);
            #pragma unroll
            for (int j = 0; j < 4; j++) ldsm_x2(base + 128 + j*32, kfl + 2*j);
            float* d = nt ? dd1 : dd0;
            #pragma unroll
            for (int t = 0; t < 4; t++) mma16816(d, afr[t],   kfh + 2*t);
            #pragma unroll
            for (int t = 0; t < 4; t++) mma16816(d, afr[t],   kfl + 2*t);
            #pragma unroll
            for (int t = 0; t < 4; t++) mma16816(d, afr[4+t], kfh + 2*t);
        }
        // scale + bias
        dd0[0] = fmaf(dd0[0], 0.125f, u00.x); dd0[1] = fmaf(dd0[1], 0.125f, u00.y);
        dd0[2] = fmaf(dd0[2], 0.125f, u10.x); dd0[3] = fmaf(dd0[3], 0.125f, u10.y);
        dd1[0] = fmaf(dd1[0], 0.125f, u01.x); dd1[1] = fmaf(dd1[1], 0.125f, u01.y);
        dd1[2] = fmaf(dd1[2], 0.125f, u11.x); dd1[3] = fmaf(dd1[3], 0.125f, u11.y);

        // ---- online softmax ----
        float rm0 = fmaxf(fmaxf(dd0[0], dd0[1]), fmaxf(dd1[0], dd1[1]));
        float rm1 = fmaxf(fmaxf(dd0[2], dd0[3]), fmaxf(dd1[2], dd1[3]));
        rm0 = fmaxf(rm0, __shfl_xor_sync(~0u, rm0, 1));
        rm0 = fmaxf(rm0, __shfl_xor_sync(~0u, rm0, 2));
        rm1 = fmaxf(rm1, __shfl_xor_sync(~0u, rm1, 1));
        rm1 = fmaxf(rm1, __shfl_xor_sync(~0u, rm1, 2));
        float M0 = fmaxf(m0, rm0), M1 = fmaxf(m1, rm1);
        float sc0 = fexp(m0 - M0), sc1 = fexp(m1 - M1);
        dd0[0] = fexp(dd0[0] - M0); dd0[1] = fexp(dd0[1] - M0);
        dd0[2] = fexp(dd0[2] - M1); dd0[3] = fexp(dd0[3] - M1);
        dd1[0] = fexp(dd1[0] - M0); dd1[1] = fexp(dd1[1] - M0);
        dd1[2] = fexp(dd1[2] - M1); dd1[3] = fexp(dd1[3] - M1);
        float ps0 = dd0[0] + dd0[1] + dd1[0] + dd1[1];
        float ps1 = dd0[2] + dd0[3] + dd1[2] + dd1[3];
        ps0 += __shfl_xor_sync(~0u, ps0, 1); ps0 += __shfl_xor_sync(~0u, ps0, 2);
        ps1 += __shfl_xor_sync(~0u, ps1, 1); ps1 += __shfl_xor_sync(~0u, ps1, 2);
        sum0 = sum0 * sc0 + ps0;
        sum1 = sum1 * sc1 + ps1;
        m0 = M0; m1 = M1;
        #pragma unroll
        for (int i = 0; i < 8; i++) {
            acc[i][0] *= sc0; acc[i][1] *= sc0;
            acc[i][2] *= sc1; acc[i][3] *= sc1;
        }
        // P fragments directly from registers (mma C layout == mma A layout)
        uint32_t phi[4], plo[4];
        psplit(dd0[0], dd0[1], phi[0], plo[0]);
        psplit(dd0[2], dd0[3], phi[1], plo[1]);
        psplit(dd1[0], dd1[1], phi[2], plo[2]);
        psplit(dd1[2], dd1[3], phi[3], plo[3]);

        __syncthreads();                                   // done reading bufA (K_c)
        if (c < 7) { ld_chunk128(bufA, Kbh, (c + 1) * 128); CP_COMMIT(); CP_WAIT1(); }
        else       { CP_WAIT0(); }                         // V_c done
        __syncthreads();

        // ---- PV from bufB ----
        #pragma unroll
        for (int hd = 0; hd < 2; hd++) {
            uint32_t vaddr = bufB + (uint32_t)((wid*16 + ((lane >> 3) & 1)*8 + (lane & 7)) * 272
                                               + ((lane >> 4) & 1) * 16 + hd*64);
            uint32_t vfh[4][2], vfl[4][2];
            #pragma unroll
            for (int p = 0; p < 2; p++) {
                uint32_t r4[4];
                ldsm_x4t(vaddr + p*32, r4);
                vfh[2*p][0] = r4[0]; vfh[2*p][1] = r4[1];
                vfh[2*p+1][0] = r4[2]; vfh[2*p+1][1] = r4[3];
                ldsm_x4t(vaddr + 128 + p*32, r4);
                vfl[2*p][0] = r4[0]; vfl[2*p][1] = r4[1];
                vfl[2*p+1][0] = r4[2]; vfl[2*p+1][1] = r4[3];
            }
            #pragma unroll
            for (int nt = 0; nt < 4; nt++) {
                mma16816(acc[hd*4 + nt], phi, vfh[nt]);
                mma16816(acc[hd*4 + nt], phi, vfl[nt]);
                mma16816(acc[hd*4 + nt], plo, vfh[nt]);
            }
        }
        __syncthreads();                                   // done reading bufB (V_c)
        if (c < 7) { ld_chunk128(bufB, Vbh, (c + 1) * 128); CP_COMMIT(); }
    }

    // ---- flash merge across 8 warps ----
    if ((lane & 3) == 0) {
        mrow[wid*16 + r_]     = m0;  srow[wid*16 + r_]     = sum0;
        mrow[wid*16 + r_ + 8] = m1;  srow[wid*16 + r_ + 8] = sum1;
    }
    __syncthreads();
    float M0g = -1e30f, M1g = -1e30f;
    #pragma unroll
    for (int w = 0; w < 8; w++) {
        M0g = fmaxf(M0g, mrow[w*16 + r_]);
        M1g = fmaxf(M1g, mrow[w*16 + r_ + 8]);
    }
    float S0g = 0.f, S1g = 0.f;
    #pragma unroll
    for (int w = 0; w < 8; w++) {
        S0g += srow[w*16 + r_]     * fexp(mrow[w*16 + r_]     - M0g);
        S1g += srow[w*16 + r_ + 8] * fexp(mrow[w*16 + r_ + 8] - M1g);
    }
    if (wid == 0 && (lane & 3) == 0) { Sfin[r_] = S0g; Sfin[r_ + 8] = S1g; }
    float f0 = fexp(m0 - M0g), f1 = fexp(m1 - M1g);
    // scaled partials into part[wid][16][64] (overlays bufA; last bufA read was S7, synced)
    #pragma unroll
    for (int i = 0; i < 8; i++) {
        int hd = i >> 2, nt = i & 3;
        int d = hd*32 + nt*8 + cl;
        *(float2*)(part + wid*1024 + r_*64 + d) =
            make_float2(acc[i][0] * f0, acc[i][1] * f0);
        *(float2*)(part + wid*1024 + (r_+8)*64 + d) =
            make_float2(acc[i][2] * f1, acc[i][3] * f1);
    }
    __syncthreads();
    for (int o = tid; o < 1024; o += 256) {
        float s = 0.f;
        #pragma unroll
        for (int w = 0; w < 8; w++) s += part[w*1024 + o];
        int qi = o >> 6, d = o & 63;
        s /= Sfin[qi];
        int col = h * 64 + d;
        split3(out + (size_t)(b * Nn + q0 + qi) * KCAT + col, s);
    }
}

// -------------------- launch --------------------
extern "C" void kernel_launch(void* const* d_in, const int* in_sizes, int n_in,
                              void* d_out, int out_size)
{
    const float* node = (const float*)d_in[0];
    const float* adj  = (const float*)d_in[1];
    const float* wd   = (const float*)d_in[2];
    const float* bear = (const float*)d_in[3];
    const float* Wq   = (const float*)d_in[4];
    const float* Wk   = (const float*)d_in[5];
    const float* Wv   = (const float*)d_in[6];
    const float* Wo   = (const float*)d_in[7];
    const float* lng  = (const float*)d_in[8];
    const float* lnb  = (const float*)d_in[9];
    const float* ww   = (const float*)d_in[10];
    const float* wbv  = (const float*)d_in[11];
    float* out = (float*)d_out;

    __nv_bfloat16 *xcat, *wqkv, *wocat, *aocat, *Qc, *Kc, *Vc;
    float *biasp, *cosp, *sinp;
    cudaGetSymbolAddress((void**)&xcat,  g_xcat);
    cudaGetSymbolAddress((void**)&wqkv,  g_wqkv);
    cudaGetSymbolAddress((void**)&wocat, g_wocat);
    cudaGetSymbolAddress((void**)&aocat, g_aocat);
    cudaGetSymbolAddress((void**)&Qc,    g_Qc);
    cudaGetSymbolAddress((void**)&Kc,    g_Kc);
    cudaGetSymbolAddress((void**)&Vc,    g_Vc);
    cudaGetSymbolAddress((void**)&biasp, g_bias);
    cudaGetSymbolAddress((void**)&cosp,  g_cos);
    cudaGetSymbolAddress((void**)&sinp,  g_sin);

    const int SMEM_GEMM = 3 * STG;
    const int SMEM_ATTN = 4352 + 2*34816 + (128 + 128 + 16) * 4;  // 75136
    cudaFuncSetAttribute(gemm_mma<0>, cudaFuncAttributeMaxDynamicSharedMemorySize, SMEM_GEMM);
    cudaFuncSetAttribute(gemm_mma<1>, cudaFuncAttributeMaxDynamicSharedMemorySize, SMEM_GEMM);
    cudaFuncSetAttribute(attn_flash,  cudaFuncAttributeMaxDynamicSharedMemorySize, SMEM_ATTN);

    prep_kernel<<<NB_WQKV + NB_WO + NB_ROPE + BN, 256>>>(Wq, Wk, Wv, Wo, node, lng, lnb,
                                                         wqkv, wocat, cosp, sinp, xcat);
    bias_kernel<<<dim3(1024, Bq), 256>>>(bear, wd, adj, ww, wbv, biasp);
    gemm_mma<0><<<dim3(KCAT/128, BN/128), 256, SMEM_GEMM>>>(xcat, wqkv, cosp, sinp,
                                                            nullptr, Qc, Kc, Vc);
    attn_flash<<<dim3(Nn/16, Hh, Bq), 256, SMEM_ATTN>>>(Qc, Kc, Vc, biasp, aocat);
    gemm_mma<1><<<dim3(Dm/128, BN/128), 256, SMEM_GEMM>>>(aocat, wocat, cosp, sinp,
                                                          node, out, nullptr, nullptr);
}